// round 2
// baseline (speedup 1.0000x reference)
#include <cuda_runtime.h>
#include <math.h>

#define B_  2
#define N_  2048
#define E_  1024
#define H_  16
#define HD_ 64

// Scratch (device globals — no runtime allocation allowed)
__device__ float g_q[(size_t)B_ * H_ * N_ * HD_];
__device__ float g_k[(size_t)B_ * H_ * N_ * HD_];
__device__ float g_v[(size_t)B_ * H_ * N_ * HD_];
__device__ float g_sa[(size_t)B_ * N_ * E_];

// ---------------------------------------------------------------------------
// QKV projection: per (b,h,part) C[64n x 64f] = X[64n x 1024] @ Wqkv[1024 x 64] + b
// part 0 = K, 1 = Q, 2 = V   (reference does k, q, v = split(proj))
// ---------------------------------------------------------------------------
__global__ __launch_bounds__(256) void qkv_kernel(
    const float* __restrict__ x, const float* __restrict__ Wqkv,
    const float* __restrict__ bqkv)
{
    __shared__ float As[16][64];
    __shared__ float Bs[16][64];
    const int tid = threadIdx.x;
    const int ty = tid >> 4, tx = tid & 15;
    const int n0 = blockIdx.x << 6;
    const int part = blockIdx.y;
    const int bh = blockIdx.z;
    const int b = bh >> 4, h = bh & 15;

    const float* Ap = x + ((size_t)b * N_ + n0) * E_;
    const float* Bp = Wqkv + (size_t)h * E_ * 192 + part * HD_;

    const int ai = tid >> 2;          // 0..63  (row of A tile)
    const int ak = (tid & 3) << 2;    // 0,4,8,12 (k quad)
    const int bk = tid >> 4;          // 0..15  (k of B tile)
    const int bj = (tid & 15) << 2;   // 0..60  (col quad)

    float acc[4][4];
#pragma unroll
    for (int u = 0; u < 4; u++)
#pragma unroll
        for (int v = 0; v < 4; v++) acc[u][v] = 0.f;

    for (int k0 = 0; k0 < E_; k0 += 16) {
        float4 av = *(const float4*)(Ap + (size_t)ai * E_ + k0 + ak);
        As[ak + 0][ai] = av.x;
        As[ak + 1][ai] = av.y;
        As[ak + 2][ai] = av.z;
        As[ak + 3][ai] = av.w;
        *(float4*)&Bs[bk][bj] =
            *(const float4*)(Bp + (size_t)(k0 + bk) * 192 + bj);
        __syncthreads();
#pragma unroll
        for (int kk = 0; kk < 16; kk++) {
            float ra[4], rb[4];
            *(float4*)ra = *(const float4*)&As[kk][ty << 2];
            *(float4*)rb = *(const float4*)&Bs[kk][tx << 2];
#pragma unroll
            for (int u = 0; u < 4; u++)
#pragma unroll
                for (int v = 0; v < 4; v++)
                    acc[u][v] = fmaf(ra[u], rb[v], acc[u][v]);
        }
        __syncthreads();
    }

    float* dst = (part == 0) ? g_k : (part == 1) ? g_q : g_v;
    dst += ((size_t)bh * N_ + n0) * HD_;
    const float* bias = bqkv + h * 192 + part * HD_;
#pragma unroll
    for (int u = 0; u < 4; u++) {
        const int row = (ty << 2) + u;
#pragma unroll
        for (int v = 0; v < 4; v++) {
            const int col = (tx << 2) + v;
            dst[row * HD_ + col] = acc[u][v] + bias[col];
        }
    }
}

// ---------------------------------------------------------------------------
// Flash attention: one block per (query 64-tile, b*h). Online softmax.
// smem: Qs + Ks + Vs = 48KB exactly; P reuses the Ks buffer.
// ---------------------------------------------------------------------------
__global__ __launch_bounds__(256) void attn_kernel()
{
    __shared__ float Qs[64][64];
    __shared__ float Ks[64][64];   // reused as P after S is consumed
    __shared__ float Vs[64][64];
    const int tid = threadIdx.x;
    const int ty = tid >> 4, tx = tid & 15;
    const int qt = blockIdx.x;
    const int bh = blockIdx.y;
    const int b = bh >> 4, h = bh & 15;
    const int q0 = qt << 6;

    const float* Qg = g_q + ((size_t)bh * N_ + q0) * HD_;
    const float* Kg = g_k + (size_t)bh * N_ * HD_;
    const float* Vg = g_v + (size_t)bh * N_ * HD_;

#pragma unroll
    for (int r = 0; r < 4; r++) {
        const int idx = (r << 8) + tid;
        const int row = idx >> 4;
        const int dq = (idx & 15) << 2;
        *(float4*)&Qs[row][dq] = *(const float4*)(Qg + row * HD_ + dq);
    }

    float m[4], l[4], O[4][4];
#pragma unroll
    for (int u = 0; u < 4; u++) {
        m[u] = -INFINITY;
        l[u] = 0.f;
#pragma unroll
        for (int v = 0; v < 4; v++) O[u][v] = 0.f;
    }
    __syncthreads();

    for (int kt = 0; kt <= qt; kt++) {
        const int k0 = kt << 6;
#pragma unroll
        for (int r = 0; r < 4; r++) {
            const int idx = (r << 8) + tid;
            const int row = idx >> 4;
            const int dq = (idx & 15) << 2;
            *(float4*)&Ks[row][dq] =
                *(const float4*)(Kg + (size_t)(k0 + row) * HD_ + dq);
            *(float4*)&Vs[row][dq] =
                *(const float4*)(Vg + (size_t)(k0 + row) * HD_ + dq);
        }
        __syncthreads();

        // S = Q @ K^T  (4x4 per thread)
        float S[4][4];
#pragma unroll
        for (int u = 0; u < 4; u++)
#pragma unroll
            for (int v = 0; v < 4; v++) S[u][v] = 0.f;

        for (int d = 0; d < 64; d += 4) {
            float rq[4][4], rk[4][4];
#pragma unroll
            for (int u = 0; u < 4; u++)
                *(float4*)rq[u] = *(const float4*)&Qs[(ty << 2) + u][d];
#pragma unroll
            for (int v = 0; v < 4; v++)
                *(float4*)rk[v] = *(const float4*)&Ks[(tx << 2) + v][d];
#pragma unroll
            for (int u = 0; u < 4; u++)
#pragma unroll
                for (int v = 0; v < 4; v++)
#pragma unroll
                    for (int dd = 0; dd < 4; dd++)
                        S[u][v] = fmaf(rq[u][dd], rk[v][dd], S[u][v]);
        }

        // scale + causal mask + online softmax (row groups = 16 lanes)
        const bool diag = (kt == qt);
#pragma unroll
        for (int u = 0; u < 4; u++) {
            const int qi = q0 + (ty << 2) + u;
            float tmax = -INFINITY;
#pragma unroll
            for (int v = 0; v < 4; v++) {
                float s = S[u][v] * 0.125f;   // 1/sqrt(64)
                if (diag && (k0 + (tx << 2) + v > qi)) s = -INFINITY;
                S[u][v] = s;
                tmax = fmaxf(tmax, s);
            }
#pragma unroll
            for (int off = 8; off > 0; off >>= 1)
                tmax = fmaxf(tmax, __shfl_xor_sync(0xffffffffu, tmax, off));
            const float mn = fmaxf(m[u], tmax);
            const float alpha = __expf(m[u] - mn);   // 0 on first tile
            float rsum = 0.f;
#pragma unroll
            for (int v = 0; v < 4; v++) {
                const float p = __expf(S[u][v] - mn);
                S[u][v] = p;
                rsum += p;
            }
#pragma unroll
            for (int off = 8; off > 0; off >>= 1)
                rsum += __shfl_xor_sync(0xffffffffu, rsum, off);
            l[u] = l[u] * alpha + rsum;
            m[u] = mn;
#pragma unroll
            for (int v = 0; v < 4; v++) O[u][v] *= alpha;
        }

        __syncthreads();   // everyone done reading Ks
#pragma unroll
        for (int u = 0; u < 4; u++)
            *(float4*)&Ks[(ty << 2) + u][tx << 2] =
                make_float4(S[u][0], S[u][1], S[u][2], S[u][3]);
        __syncthreads();

        // O += P @ V
        for (int j = 0; j < 64; j += 4) {
            float rp[4][4];
#pragma unroll
            for (int u = 0; u < 4; u++)
                *(float4*)rp[u] = *(const float4*)&Ks[(ty << 2) + u][j];
#pragma unroll
            for (int jj = 0; jj < 4; jj++) {
                float rv[4];
                *(float4*)rv = *(const float4*)&Vs[j + jj][tx << 2];
#pragma unroll
                for (int u = 0; u < 4; u++)
#pragma unroll
                    for (int v = 0; v < 4; v++)
                        O[u][v] = fmaf(rp[u][jj], rv[v], O[u][v]);
            }
        }
        __syncthreads();   // done with Ks/Vs before next tile load
    }

    // normalize and write heads-concatenated layout sa[b, n, h*64+d]
    float* dst = g_sa + ((size_t)b * N_ + q0) * E_ + h * HD_;
#pragma unroll
    for (int u = 0; u < 4; u++) {
        const float inv = 1.f / l[u];
        const int row = (ty << 2) + u;
#pragma unroll
        for (int v = 0; v < 4; v++)
            dst[(size_t)row * E_ + (tx << 2) + v] = O[u][v] * inv;
    }
}

// ---------------------------------------------------------------------------
// Output projection: out[4096 x 1024] = sa @ Wout + bout
// ---------------------------------------------------------------------------
__global__ __launch_bounds__(256) void outproj_kernel(
    const float* __restrict__ Wout, const float* __restrict__ bout,
    float* __restrict__ out)
{
    __shared__ float As[16][64];
    __shared__ float Bs[16][64];
    const int tid = threadIdx.x;
    const int ty = tid >> 4, tx = tid & 15;
    const int r0 = blockIdx.x << 6;
    const int c0 = blockIdx.y << 6;

    const float* Ap = g_sa + (size_t)r0 * E_;
    const float* Bp = Wout + c0;

    const int ai = tid >> 2;
    const int ak = (tid & 3) << 2;
    const int bk = tid >> 4;
    const int bj = (tid & 15) << 2;

    float acc[4][4];
#pragma unroll
    for (int u = 0; u < 4; u++)
#pragma unroll
        for (int v = 0; v < 4; v++) acc[u][v] = 0.f;

    for (int k0 = 0; k0 < E_; k0 += 16) {
        float4 av = *(const float4*)(Ap + (size_t)ai * E_ + k0 + ak);
        As[ak + 0][ai] = av.x;
        As[ak + 1][ai] = av.y;
        As[ak + 2][ai] = av.z;
        As[ak + 3][ai] = av.w;
        *(float4*)&Bs[bk][bj] =
            *(const float4*)(Bp + (size_t)(k0 + bk) * E_ + bj);
        __syncthreads();
#pragma unroll
        for (int kk = 0; kk < 16; kk++) {
            float ra[4], rb[4];
            *(float4*)ra = *(const float4*)&As[kk][ty << 2];
            *(float4*)rb = *(const float4*)&Bs[kk][tx << 2];
#pragma unroll
            for (int u = 0; u < 4; u++)
#pragma unroll
                for (int v = 0; v < 4; v++)
                    acc[u][v] = fmaf(ra[u], rb[v], acc[u][v]);
        }
        __syncthreads();
    }

#pragma unroll
    for (int u = 0; u < 4; u++) {
        const int row = (ty << 2) + u;
#pragma unroll
        for (int v = 0; v < 4; v++) {
            const int col = (tx << 2) + v;
            out[(size_t)(r0 + row) * E_ + c0 + col] = acc[u][v] + bout[c0 + col];
        }
    }
}

// ---------------------------------------------------------------------------
extern "C" void kernel_launch(void* const* d_in, const int* in_sizes, int n_in,
                              void* d_out, int out_size)
{
    // Resolve inputs by element count (all distinct) for metadata robustness.
    const float* x = nullptr;
    const float* Wqkv = nullptr;
    const float* bqkv = nullptr;
    const float* Wout = nullptr;
    const float* bout = nullptr;
    for (int i = 0; i < n_in; i++) {
        switch (in_sizes[i]) {
            case B_ * N_ * E_:        x    = (const float*)d_in[i]; break; // 4194304
            case H_ * E_ * 3 * HD_:   Wqkv = (const float*)d_in[i]; break; // 3145728
            case H_ * 3 * HD_:        bqkv = (const float*)d_in[i]; break; // 3072
            case E_ * E_:             Wout = (const float*)d_in[i]; break; // 1048576
            case E_:                  bout = (const float*)d_in[i]; break; // 1024
            default: break;
        }
    }
    float* out = (float*)d_out;

    qkv_kernel<<<dim3(N_ / 64, 3, B_ * H_), 256>>>(x, Wqkv, bqkv);
    attn_kernel<<<dim3(N_ / 64, B_ * H_), 256>>>();
    outproj_kernel<<<dim3((B_ * N_) / 64, E_ / 64), 256>>>(Wout, bout, out);
}

// round 3
// speedup vs baseline: 4.8176x; 4.8176x over previous
#include <cuda_runtime.h>
#include <math.h>
#include <stdint.h>

#define B_  2
#define N_  2048
#define E_  1024
#define H_  16
#define HD_ 64

#define NEG_INF __int_as_float(0xff800000)

// Scratch (device globals — no runtime allocation allowed)
__device__ float g_q[(size_t)B_ * H_ * N_ * HD_];
__device__ float g_k[(size_t)B_ * H_ * N_ * HD_];
__device__ float g_v[(size_t)B_ * H_ * N_ * HD_];
__device__ float g_sa[(size_t)B_ * N_ * E_];

// ---------------------------------------------------------------------------
// helpers
// ---------------------------------------------------------------------------
__device__ __forceinline__ uint32_t tf32u(float x) {
    uint32_t u;
    asm("cvt.rna.tf32.f32 %0, %1;" : "=r"(u) : "f"(x));
    return u;
}
__device__ __forceinline__ float tf32f(float x) {
    return __uint_as_float(tf32u(x));
}

__device__ __forceinline__ void mma_tf32(float (&d)[4], const uint32_t (&a)[4],
                                         const uint32_t (&b)[2]) {
    asm volatile(
        "mma.sync.aligned.m16n8k8.row.col.f32.tf32.tf32.f32 "
        "{%0,%1,%2,%3},{%4,%5,%6,%7},{%8,%9},{%0,%1,%2,%3};"
        : "+f"(d[0]), "+f"(d[1]), "+f"(d[2]), "+f"(d[3])
        : "r"(a[0]), "r"(a[1]), "r"(a[2]), "r"(a[3]), "r"(b[0]), "r"(b[1]));
}

// ---------------------------------------------------------------------------
// Generic 128x64 GEMM tile: C = A[128 x 1024] @ B[1024 x 64] + bias
// A row-major lda=1024, B row-major with given ldb, C row-major ldc.
// ---------------------------------------------------------------------------
__device__ __forceinline__ void gemm_tile_128x64(
    const float* __restrict__ A, const float* __restrict__ B, int ldb,
    const float* __restrict__ bias, float* __restrict__ C, int ldc)
{
    __shared__ float As[128][36];
    __shared__ float Bs[32][68];

    const int tid = threadIdx.x;
    const int lane = tid & 31, wid = tid >> 5;
    const int gid = lane >> 2, tig = lane & 3;
    const int wm = wid >> 1, wn = wid & 1;

    float acc[2][4][4];
#pragma unroll
    for (int mt = 0; mt < 2; mt++)
#pragma unroll
        for (int nt = 0; nt < 4; nt++)
#pragma unroll
            for (int j = 0; j < 4; j++) acc[mt][nt][j] = 0.f;

    for (int kc = 0; kc < E_; kc += 32) {
#pragma unroll
        for (int j = 0; j < 4; j++) {
            const int idx = tid + j * 256;       // 0..1023
            const int row = idx >> 3, c4 = (idx & 7) << 2;
            float4 v = *(const float4*)(A + (size_t)row * E_ + kc + c4);
            As[row][c4 + 0] = tf32f(v.x);
            As[row][c4 + 1] = tf32f(v.y);
            As[row][c4 + 2] = tf32f(v.z);
            As[row][c4 + 3] = tf32f(v.w);
        }
#pragma unroll
        for (int j = 0; j < 2; j++) {
            const int idx = tid + j * 256;       // 0..511
            const int row = idx >> 4, c4 = (idx & 15) << 2;
            float4 v = *(const float4*)(B + (size_t)(kc + row) * ldb + c4);
            Bs[row][c4 + 0] = tf32f(v.x);
            Bs[row][c4 + 1] = tf32f(v.y);
            Bs[row][c4 + 2] = tf32f(v.z);
            Bs[row][c4 + 3] = tf32f(v.w);
        }
        __syncthreads();

#pragma unroll
        for (int kk = 0; kk < 4; kk++) {
            uint32_t a[2][4], b[4][2];
#pragma unroll
            for (int mt = 0; mt < 2; mt++) {
                const int rb = wm * 32 + mt * 16;
                a[mt][0] = __float_as_uint(As[rb + gid][kk * 8 + tig]);
                a[mt][1] = __float_as_uint(As[rb + 8 + gid][kk * 8 + tig]);
                a[mt][2] = __float_as_uint(As[rb + gid][kk * 8 + tig + 4]);
                a[mt][3] = __float_as_uint(As[rb + 8 + gid][kk * 8 + tig + 4]);
            }
#pragma unroll
            for (int nt = 0; nt < 4; nt++) {
                const int col = wn * 32 + nt * 8 + gid;
                b[nt][0] = __float_as_uint(Bs[kk * 8 + tig][col]);
                b[nt][1] = __float_as_uint(Bs[kk * 8 + tig + 4][col]);
            }
#pragma unroll
            for (int mt = 0; mt < 2; mt++)
#pragma unroll
                for (int nt = 0; nt < 4; nt++)
                    mma_tf32(acc[mt][nt], a[mt], b[nt]);
        }
        __syncthreads();
    }

#pragma unroll
    for (int mt = 0; mt < 2; mt++) {
        const int row = wm * 32 + mt * 16 + gid;
#pragma unroll
        for (int nt = 0; nt < 4; nt++) {
            const int col = wn * 32 + nt * 8 + 2 * tig;
            const float b0 = bias[col], b1 = bias[col + 1];
            float2 lo = make_float2(acc[mt][nt][0] + b0, acc[mt][nt][1] + b1);
            float2 hi = make_float2(acc[mt][nt][2] + b0, acc[mt][nt][3] + b1);
            *(float2*)&C[(size_t)row * ldc + col] = lo;
            *(float2*)&C[(size_t)(row + 8) * ldc + col] = hi;
        }
    }
}

// ---------------------------------------------------------------------------
// QKV projection: per (b,h,part): [2048 x 1024] @ [1024 x 64] + bias
// part 0 = K, 1 = Q, 2 = V (reference splits k,q,v in that order)
// ---------------------------------------------------------------------------
__global__ __launch_bounds__(256) void qkv_kernel(
    const float* __restrict__ x, const float* __restrict__ Wqkv,
    const float* __restrict__ bqkv)
{
    const int n0 = blockIdx.x << 7;
    const int part = blockIdx.y;
    const int bh = blockIdx.z;
    const int b = bh >> 4, h = bh & 15;

    const float* A = x + ((size_t)b * N_ + n0) * E_;
    const float* Bp = Wqkv + (size_t)h * E_ * 192 + part * HD_;
    const float* bias = bqkv + h * 192 + part * HD_;
    float* dst = ((part == 0) ? g_k : (part == 1) ? g_q : g_v) +
                 ((size_t)bh * N_ + n0) * HD_;

    gemm_tile_128x64(A, Bp, 192, bias, dst, HD_);
}

// ---------------------------------------------------------------------------
// Output projection: out[4096 x 1024] = g_sa @ Wout + bout
// ---------------------------------------------------------------------------
__global__ __launch_bounds__(256) void outproj_kernel(
    const float* __restrict__ Wout, const float* __restrict__ bout,
    float* __restrict__ out)
{
    const int r0 = blockIdx.x << 7;
    const int c0 = blockIdx.y << 6;
    gemm_tile_128x64(g_sa + (size_t)r0 * E_, Wout + c0, E_, bout + c0,
                     out + (size_t)r0 * E_ + c0, E_);
}

// ---------------------------------------------------------------------------
// Flash attention, TF32 tensor cores. Block = 128 queries, 8 warps,
// each warp owns 16 query rows x full 64-key tile (8 n-tiles of m16n8k8).
// ---------------------------------------------------------------------------
__global__ __launch_bounds__(256) void attn_kernel()
{
    __shared__ float Ks[64][68];
    __shared__ float Vs[64][68];

    const int tid = threadIdx.x;
    const int lane = tid & 31, wid = tid >> 5;
    const int gid = lane >> 2, tig = lane & 3;
    const int qt = blockIdx.x;
    const int bh = blockIdx.y;
    const int b = bh >> 4, h = bh & 15;
    const int q0 = qt << 7;

    const float* Qg = g_q + ((size_t)bh * N_ + q0) * HD_;
    const float* Kg = g_k + (size_t)bh * N_ * HD_;
    const float* Vg = g_v + (size_t)bh * N_ * HD_;

    // ---- stage Q (scaled by 1/8, tf32) in two 64-row halves through Ks ----
    uint32_t Qa[8][4];
#pragma unroll
    for (int half = 0; half < 2; half++) {
#pragma unroll
        for (int j = 0; j < 4; j++) {
            const int idx = tid + j * 256;
            const int row = idx >> 4, c4 = (idx & 15) << 2;
            float4 v = *(const float4*)(Qg + (size_t)(half * 64 + row) * HD_ + c4);
            Ks[row][c4 + 0] = tf32f(v.x * 0.125f);
            Ks[row][c4 + 1] = tf32f(v.y * 0.125f);
            Ks[row][c4 + 2] = tf32f(v.z * 0.125f);
            Ks[row][c4 + 3] = tf32f(v.w * 0.125f);
        }
        __syncthreads();
        if ((wid >> 2) == half) {
            const int lr = (wid & 3) * 16 + gid;
#pragma unroll
            for (int kk = 0; kk < 8; kk++) {
                Qa[kk][0] = __float_as_uint(Ks[lr][kk * 8 + tig]);
                Qa[kk][1] = __float_as_uint(Ks[lr + 8][kk * 8 + tig]);
                Qa[kk][2] = __float_as_uint(Ks[lr][kk * 8 + tig + 4]);
                Qa[kk][3] = __float_as_uint(Ks[lr + 8][kk * 8 + tig + 4]);
            }
        }
        __syncthreads();
    }

    float m_[2] = {NEG_INF, NEG_INF};
    float l_[2] = {0.f, 0.f};
    float Of[8][4];
#pragma unroll
    for (int nt = 0; nt < 8; nt++)
#pragma unroll
        for (int j = 0; j < 4; j++) Of[nt][j] = 0.f;

    const int row0 = q0 + wid * 16 + gid;     // u=0 row; +8 for u=1
    const int wrow_max = q0 + wid * 16 + 15;  // last row this warp owns
    const int nkt = 2 * qt + 2;

    for (int kt = 0; kt < nkt; kt++) {
        const int k0 = kt << 6;
        // ---- stage K, V (tf32) ----
#pragma unroll
        for (int j = 0; j < 4; j++) {
            const int idx = tid + j * 256;
            const int row = idx >> 4, c4 = (idx & 15) << 2;
            float4 kv = *(const float4*)(Kg + (size_t)(k0 + row) * HD_ + c4);
            Ks[row][c4 + 0] = tf32f(kv.x);
            Ks[row][c4 + 1] = tf32f(kv.y);
            Ks[row][c4 + 2] = tf32f(kv.z);
            Ks[row][c4 + 3] = tf32f(kv.w);
            float4 vv = *(const float4*)(Vg + (size_t)(k0 + row) * HD_ + c4);
            Vs[row][c4 + 0] = tf32f(vv.x);
            Vs[row][c4 + 1] = tf32f(vv.y);
            Vs[row][c4 + 2] = tf32f(vv.z);
            Vs[row][c4 + 3] = tf32f(vv.w);
        }
        __syncthreads();

        if (k0 <= wrow_max) {   // warp has at least one unmasked column
            // ---- S = Q @ K^T ----
            float Sf[8][4];
#pragma unroll
            for (int nt = 0; nt < 8; nt++)
#pragma unroll
                for (int j = 0; j < 4; j++) Sf[nt][j] = 0.f;

#pragma unroll
            for (int kk = 0; kk < 8; kk++) {
#pragma unroll
                for (int nt = 0; nt < 8; nt++) {
                    uint32_t bb[2];
                    bb[0] = __float_as_uint(Ks[nt * 8 + gid][kk * 8 + tig]);
                    bb[1] = __float_as_uint(Ks[nt * 8 + gid][kk * 8 + tig + 4]);
                    mma_tf32(Sf[nt], Qa[kk], bb);
                }
            }

            // ---- online softmax on C-fragments (row = 4-lane group) ----
#pragma unroll
            for (int u = 0; u < 2; u++) {
                const int row = row0 + u * 8;
                float tmax = NEG_INF;
#pragma unroll
                for (int nt = 0; nt < 8; nt++)
#pragma unroll
                    for (int j = 0; j < 2; j++) {
                        const int col = k0 + nt * 8 + 2 * tig + j;
                        float s = Sf[nt][u * 2 + j];
                        if (col > row) s = NEG_INF;
                        Sf[nt][u * 2 + j] = s;
                        tmax = fmaxf(tmax, s);
                    }
                tmax = fmaxf(tmax, __shfl_xor_sync(0xffffffffu, tmax, 1));
                tmax = fmaxf(tmax, __shfl_xor_sync(0xffffffffu, tmax, 2));
                const float mn = fmaxf(m_[u], tmax);
                const float alpha = __expf(m_[u] - mn);
                float rsum = 0.f;
#pragma unroll
                for (int nt = 0; nt < 8; nt++)
#pragma unroll
                    for (int j = 0; j < 2; j++) {
                        const float p = __expf(Sf[nt][u * 2 + j] - mn);
                        Sf[nt][u * 2 + j] = p;
                        rsum += p;
                    }
                rsum += __shfl_xor_sync(0xffffffffu, rsum, 1);
                rsum += __shfl_xor_sync(0xffffffffu, rsum, 2);
                l_[u] = l_[u] * alpha + rsum;
                m_[u] = mn;
#pragma unroll
                for (int nt = 0; nt < 8; nt++)
#pragma unroll
                    for (int j = 0; j < 2; j++) Of[nt][u * 2 + j] *= alpha;
            }

            // ---- O += P @ V  (C-frag -> A-frag via shuffles, tf32) ----
#pragma unroll
            for (int kk = 0; kk < 8; kk++) {
                const int src = (lane & 28) | (tig >> 1);
                const int src2 = src + 2;
                const float e0 = __shfl_sync(0xffffffffu, Sf[kk][0], src);
                const float e1 = __shfl_sync(0xffffffffu, Sf[kk][1], src);
                const float e2 = __shfl_sync(0xffffffffu, Sf[kk][2], src);
                const float e3 = __shfl_sync(0xffffffffu, Sf[kk][3], src);
                const float f0 = __shfl_sync(0xffffffffu, Sf[kk][0], src2);
                const float f1 = __shfl_sync(0xffffffffu, Sf[kk][1], src2);
                const float f2 = __shfl_sync(0xffffffffu, Sf[kk][2], src2);
                const float f3 = __shfl_sync(0xffffffffu, Sf[kk][3], src2);
                const bool odd = tig & 1;
                uint32_t Pa[4];
                Pa[0] = tf32u(odd ? e1 : e0);
                Pa[1] = tf32u(odd ? e3 : e2);
                Pa[2] = tf32u(odd ? f1 : f0);
                Pa[3] = tf32u(odd ? f3 : f2);
#pragma unroll
                for (int nt = 0; nt < 8; nt++) {
                    uint32_t bb[2];
                    bb[0] = __float_as_uint(Vs[kk * 8 + tig][nt * 8 + gid]);
                    bb[1] = __float_as_uint(Vs[kk * 8 + tig + 4][nt * 8 + gid]);
                    mma_tf32(Of[nt], Pa, bb);
                }
            }
        }
        __syncthreads();
    }

    // ---- normalize + write heads-concatenated sa[b, n, h*64+d] ----
    const float inv0 = 1.f / l_[0];
    const float inv1 = 1.f / l_[1];
    float* dst = g_sa + ((size_t)(b * N_ + q0 + wid * 16 + gid)) * E_ + h * HD_;
#pragma unroll
    for (int nt = 0; nt < 8; nt++) {
        const int col = nt * 8 + 2 * tig;
        *(float2*)&dst[col] =
            make_float2(Of[nt][0] * inv0, Of[nt][1] * inv0);
        *(float2*)&dst[(size_t)8 * E_ + col] =
            make_float2(Of[nt][2] * inv1, Of[nt][3] * inv1);
    }
}

// ---------------------------------------------------------------------------
extern "C" void kernel_launch(void* const* d_in, const int* in_sizes, int n_in,
                              void* d_out, int out_size)
{
    const float* x = nullptr;
    const float* Wqkv = nullptr;
    const float* bqkv = nullptr;
    const float* Wout = nullptr;
    const float* bout = nullptr;
    for (int i = 0; i < n_in; i++) {
        switch (in_sizes[i]) {
            case B_ * N_ * E_:        x    = (const float*)d_in[i]; break; // 4194304
            case H_ * E_ * 3 * HD_:   Wqkv = (const float*)d_in[i]; break; // 3145728
            case H_ * 3 * HD_:        bqkv = (const float*)d_in[i]; break; // 3072
            case E_ * E_:             Wout = (const float*)d_in[i]; break; // 1048576
            case E_:                  bout = (const float*)d_in[i]; break; // 1024
            default: break;
        }
    }
    float* out = (float*)d_out;

    qkv_kernel<<<dim3(N_ / 128, 3, B_ * H_), 256>>>(x, Wqkv, bqkv);
    attn_kernel<<<dim3(N_ / 128, B_ * H_), 256>>>();
    outproj_kernel<<<dim3((B_ * N_) / 128, E_ / 64), 256>>>(Wout, bout, out);
}

// round 4
// speedup vs baseline: 5.7446x; 1.1924x over previous
#include <cuda_runtime.h>
#include <math.h>
#include <stdint.h>

#define B_  2
#define N_  2048
#define E_  1024
#define H_  16
#define HD_ 64

#define NEG_INF __int_as_float(0xff800000)

// Scratch (device globals — no runtime allocation allowed)
__device__ float g_q[(size_t)B_ * H_ * N_ * HD_];
__device__ float g_k[(size_t)B_ * H_ * N_ * HD_];
__device__ float g_v[(size_t)B_ * H_ * N_ * HD_];
__device__ float g_sa[(size_t)B_ * N_ * E_];

// ---------------------------------------------------------------------------
// helpers
// ---------------------------------------------------------------------------
__device__ __forceinline__ uint32_t tf32u(float x) {
    uint32_t u;
    asm("cvt.rna.tf32.f32 %0, %1;" : "=r"(u) : "f"(x));
    return u;
}
__device__ __forceinline__ float tf32f(float x) {
    return __uint_as_float(tf32u(x));
}
__device__ __forceinline__ float4 tf32f4(float4 v) {
    return make_float4(tf32f(v.x), tf32f(v.y), tf32f(v.z), tf32f(v.w));
}

__device__ __forceinline__ void mma_tf32(float (&d)[4], const uint32_t (&a)[4],
                                         const uint32_t (&b)[2]) {
    asm volatile(
        "mma.sync.aligned.m16n8k8.row.col.f32.tf32.tf32.f32 "
        "{%0,%1,%2,%3},{%4,%5,%6,%7},{%8,%9},{%0,%1,%2,%3};"
        : "+f"(d[0]), "+f"(d[1]), "+f"(d[2]), "+f"(d[3])
        : "r"(a[0]), "r"(a[1]), "r"(a[2]), "r"(a[3]), "r"(b[0]), "r"(b[1]));
}

// ---------------------------------------------------------------------------
// QKV projection, parts fused: block = 128 rows x 96 cols of one head's
// [2048 x 192] output. 8 warps as 2m x 4n -> warp tile 64 x 24.
// Register-prefetch pipeline; vectorized STS; conflict-free smem pitches.
// ---------------------------------------------------------------------------
__global__ __launch_bounds__(256, 2) void qkv_kernel(
    const float* __restrict__ x, const float* __restrict__ Wqkv,
    const float* __restrict__ bqkv)
{
    __shared__ float As[128][36];
    __shared__ float Bs[32][104];

    const int tid = threadIdx.x;
    const int lane = tid & 31, wid = tid >> 5;
    const int gid = lane >> 2, tig = lane & 3;
    const int wm = wid >> 2, wn = wid & 3;

    const int n0 = blockIdx.x << 7;
    const int y  = blockIdx.y;            // 96-col half of the 192 cols
    const int bh = blockIdx.z;
    const int h = bh & 15;

    const float* A = x + ((size_t)(bh >> 4) * N_ + n0) * E_;
    const float* Bg = Wqkv + (size_t)h * E_ * 192 + y * 96;

    float4 pa[4], pb[3];

    // prologue load, chunk 0
#pragma unroll
    for (int j = 0; j < 4; j++) {
        const int idx = tid + j * 256;
        pa[j] = *(const float4*)(A + (size_t)(idx >> 3) * E_ + ((idx & 7) << 2));
    }
#pragma unroll
    for (int j = 0; j < 3; j++) {
        const int idx = tid + j * 256;
        const int row = idx / 24, q = idx - row * 24;
        pb[j] = *(const float4*)(Bg + (size_t)row * 192 + q * 4);
    }

    float acc[4][3][4];
#pragma unroll
    for (int mt = 0; mt < 4; mt++)
#pragma unroll
        for (int nt = 0; nt < 3; nt++)
#pragma unroll
            for (int j = 0; j < 4; j++) acc[mt][nt][j] = 0.f;

    for (int kc = 0; kc < E_; kc += 32) {
        // store staged chunk (tf32, vectorized)
#pragma unroll
        for (int j = 0; j < 4; j++) {
            const int idx = tid + j * 256;
            *(float4*)&As[idx >> 3][(idx & 7) << 2] = tf32f4(pa[j]);
        }
#pragma unroll
        for (int j = 0; j < 3; j++) {
            const int idx = tid + j * 256;
            const int row = idx / 24, q = idx - row * 24;
            *(float4*)&Bs[row][q * 4] = tf32f4(pb[j]);
        }
        __syncthreads();

        // prefetch next chunk (in flight during mma)
        if (kc + 32 < E_) {
#pragma unroll
            for (int j = 0; j < 4; j++) {
                const int idx = tid + j * 256;
                pa[j] = *(const float4*)(A + (size_t)(idx >> 3) * E_ + kc + 32 +
                                         ((idx & 7) << 2));
            }
#pragma unroll
            for (int j = 0; j < 3; j++) {
                const int idx = tid + j * 256;
                const int row = idx / 24, q = idx - row * 24;
                pb[j] = *(const float4*)(Bg + (size_t)(kc + 32 + row) * 192 + q * 4);
            }
        }

#pragma unroll
        for (int kk = 0; kk < 4; kk++) {
            uint32_t a[4][4];
#pragma unroll
            for (int mt = 0; mt < 4; mt++) {
                const int rb = wm * 64 + mt * 16;
                a[mt][0] = __float_as_uint(As[rb + gid][kk * 8 + tig]);
                a[mt][1] = __float_as_uint(As[rb + 8 + gid][kk * 8 + tig]);
                a[mt][2] = __float_as_uint(As[rb + gid][kk * 8 + tig + 4]);
                a[mt][3] = __float_as_uint(As[rb + 8 + gid][kk * 8 + tig + 4]);
            }
            uint32_t bf[3][2];
#pragma unroll
            for (int nt = 0; nt < 3; nt++) {
                const int col = wn * 24 + nt * 8 + gid;
                bf[nt][0] = __float_as_uint(Bs[kk * 8 + tig][col]);
                bf[nt][1] = __float_as_uint(Bs[kk * 8 + tig + 4][col]);
            }
#pragma unroll
            for (int mt = 0; mt < 4; mt++)
#pragma unroll
                for (int nt = 0; nt < 3; nt++)
                    mma_tf32(acc[mt][nt], a[mt], bf[nt]);
        }
        __syncthreads();
    }

    // epilogue: route columns to K/Q/V (part = c/64), add bias
#pragma unroll
    for (int mt = 0; mt < 4; mt++) {
        const int row = n0 + wm * 64 + mt * 16 + gid;
#pragma unroll
        for (int nt = 0; nt < 3; nt++) {
            const int c = y * 96 + wn * 24 + nt * 8 + 2 * tig;
            const int part = c >> 6, cc = c & 63;
            float* base = (part == 0) ? g_k : (part == 1) ? g_q : g_v;
            const float b0 = bqkv[h * 192 + c], b1 = bqkv[h * 192 + c + 1];
            float* p = base + ((size_t)bh * N_ + row) * HD_ + cc;
            *(float2*)p = make_float2(acc[mt][nt][0] + b0, acc[mt][nt][1] + b1);
            *(float2*)(p + (size_t)8 * HD_) =
                make_float2(acc[mt][nt][2] + b0, acc[mt][nt][3] + b1);
        }
    }
}

// ---------------------------------------------------------------------------
// Output projection: block 128 x 128, 8 warps 2m x 4n -> warp 64 x 32.
// ---------------------------------------------------------------------------
__global__ __launch_bounds__(256, 2) void outproj_kernel(
    const float* __restrict__ Wout, const float* __restrict__ bout,
    float* __restrict__ out)
{
    __shared__ float As[128][36];
    __shared__ float Bs[32][136];

    const int tid = threadIdx.x;
    const int lane = tid & 31, wid = tid >> 5;
    const int gid = lane >> 2, tig = lane & 3;
    const int wm = wid >> 2, wn = wid & 3;

    const int r0 = blockIdx.x << 7;
    const int c0 = blockIdx.y << 7;

    const float* A = g_sa + (size_t)r0 * E_;
    const float* Bg = Wout + c0;

    float4 pa[4], pb[4];
#pragma unroll
    for (int j = 0; j < 4; j++) {
        const int idx = tid + j * 256;
        pa[j] = *(const float4*)(A + (size_t)(idx >> 3) * E_ + ((idx & 7) << 2));
        pb[j] = *(const float4*)(Bg + (size_t)(idx >> 5) * E_ + ((idx & 31) << 2));
    }

    float acc[4][4][4];
#pragma unroll
    for (int mt = 0; mt < 4; mt++)
#pragma unroll
        for (int nt = 0; nt < 4; nt++)
#pragma unroll
            for (int j = 0; j < 4; j++) acc[mt][nt][j] = 0.f;

    for (int kc = 0; kc < E_; kc += 32) {
#pragma unroll
        for (int j = 0; j < 4; j++) {
            const int idx = tid + j * 256;
            *(float4*)&As[idx >> 3][(idx & 7) << 2] = tf32f4(pa[j]);
            *(float4*)&Bs[idx >> 5][(idx & 31) << 2] = tf32f4(pb[j]);
        }
        __syncthreads();

        if (kc + 32 < E_) {
#pragma unroll
            for (int j = 0; j < 4; j++) {
                const int idx = tid + j * 256;
                pa[j] = *(const float4*)(A + (size_t)(idx >> 3) * E_ + kc + 32 +
                                         ((idx & 7) << 2));
                pb[j] = *(const float4*)(Bg + (size_t)(kc + 32 + (idx >> 5)) * E_ +
                                         ((idx & 31) << 2));
            }
        }

#pragma unroll
        for (int kk = 0; kk < 4; kk++) {
            uint32_t a[4][4];
#pragma unroll
            for (int mt = 0; mt < 4; mt++) {
                const int rb = wm * 64 + mt * 16;
                a[mt][0] = __float_as_uint(As[rb + gid][kk * 8 + tig]);
                a[mt][1] = __float_as_uint(As[rb + 8 + gid][kk * 8 + tig]);
                a[mt][2] = __float_as_uint(As[rb + gid][kk * 8 + tig + 4]);
                a[mt][3] = __float_as_uint(As[rb + 8 + gid][kk * 8 + tig + 4]);
            }
            uint32_t bf[4][2];
#pragma unroll
            for (int nt = 0; nt < 4; nt++) {
                const int col = wn * 32 + nt * 8 + gid;
                bf[nt][0] = __float_as_uint(Bs[kk * 8 + tig][col]);
                bf[nt][1] = __float_as_uint(Bs[kk * 8 + tig + 4][col]);
            }
#pragma unroll
            for (int mt = 0; mt < 4; mt++)
#pragma unroll
                for (int nt = 0; nt < 4; nt++)
                    mma_tf32(acc[mt][nt], a[mt], bf[nt]);
        }
        __syncthreads();
    }

#pragma unroll
    for (int mt = 0; mt < 4; mt++) {
        const int row = r0 + wm * 64 + mt * 16 + gid;
#pragma unroll
        for (int nt = 0; nt < 4; nt++) {
            const int col = c0 + wn * 32 + nt * 8 + 2 * tig;
            const float b0 = bout[col], b1 = bout[col + 1];
            *(float2*)&out[(size_t)row * E_ + col] =
                make_float2(acc[mt][nt][0] + b0, acc[mt][nt][1] + b1);
            *(float2*)&out[(size_t)(row + 8) * E_ + col] =
                make_float2(acc[mt][nt][2] + b0, acc[mt][nt][3] + b1);
        }
    }
}

// ---------------------------------------------------------------------------
// Flash attention, TF32 tensor cores. Block = 128 queries, 8 warps,
// each warp owns 16 query rows x full 64-key tile (8 n-tiles of m16n8k8).
// ---------------------------------------------------------------------------
__global__ __launch_bounds__(256) void attn_kernel()
{
    __shared__ float Ks[64][68];
    __shared__ float Vs[64][68];

    const int tid = threadIdx.x;
    const int lane = tid & 31, wid = tid >> 5;
    const int gid = lane >> 2, tig = lane & 3;
    const int qt = blockIdx.x;
    const int bh = blockIdx.y;
    const int b = bh >> 4, h = bh & 15;
    const int q0 = qt << 7;

    const float* Qg = g_q + ((size_t)bh * N_ + q0) * HD_;
    const float* Kg = g_k + (size_t)bh * N_ * HD_;
    const float* Vg = g_v + (size_t)bh * N_ * HD_;

    // ---- stage Q (scaled by 1/8, tf32) in two 64-row halves through Ks ----
    uint32_t Qa[8][4];
#pragma unroll
    for (int half = 0; half < 2; half++) {
#pragma unroll
        for (int j = 0; j < 4; j++) {
            const int idx = tid + j * 256;
            const int row = idx >> 4, c4 = (idx & 15) << 2;
            float4 v = *(const float4*)(Qg + (size_t)(half * 64 + row) * HD_ + c4);
            v.x *= 0.125f; v.y *= 0.125f; v.z *= 0.125f; v.w *= 0.125f;
            *(float4*)&Ks[row][c4] = tf32f4(v);
        }
        __syncthreads();
        if ((wid >> 2) == half) {
            const int lr = (wid & 3) * 16 + gid;
#pragma unroll
            for (int kk = 0; kk < 8; kk++) {
                Qa[kk][0] = __float_as_uint(Ks[lr][kk * 8 + tig]);
                Qa[kk][1] = __float_as_uint(Ks[lr + 8][kk * 8 + tig]);
                Qa[kk][2] = __float_as_uint(Ks[lr][kk * 8 + tig + 4]);
                Qa[kk][3] = __float_as_uint(Ks[lr + 8][kk * 8 + tig + 4]);
            }
        }
        __syncthreads();
    }

    float m_[2] = {NEG_INF, NEG_INF};
    float l_[2] = {0.f, 0.f};
    float Of[8][4];
#pragma unroll
    for (int nt = 0; nt < 8; nt++)
#pragma unroll
        for (int j = 0; j < 4; j++) Of[nt][j] = 0.f;

    const int row0 = q0 + wid * 16 + gid;     // u=0 row; +8 for u=1
    const int wrow_max = q0 + wid * 16 + 15;  // last row this warp owns
    const int nkt = 2 * qt + 2;

    for (int kt = 0; kt < nkt; kt++) {
        const int k0 = kt << 6;
        // ---- stage K, V (tf32, vectorized STS) ----
#pragma unroll
        for (int j = 0; j < 4; j++) {
            const int idx = tid + j * 256;
            const int row = idx >> 4, c4 = (idx & 15) << 2;
            float4 kv = *(const float4*)(Kg + (size_t)(k0 + row) * HD_ + c4);
            *(float4*)&Ks[row][c4] = tf32f4(kv);
            float4 vv = *(const float4*)(Vg + (size_t)(k0 + row) * HD_ + c4);
            *(float4*)&Vs[row][c4] = tf32f4(vv);
        }
        __syncthreads();

        if (k0 <= wrow_max) {   // warp has at least one unmasked column
            // ---- S = Q @ K^T ----
            float Sf[8][4];
#pragma unroll
            for (int nt = 0; nt < 8; nt++)
#pragma unroll
                for (int j = 0; j < 4; j++) Sf[nt][j] = 0.f;

#pragma unroll
            for (int kk = 0; kk < 8; kk++) {
#pragma unroll
                for (int nt = 0; nt < 8; nt++) {
                    uint32_t bb[2];
                    bb[0] = __float_as_uint(Ks[nt * 8 + gid][kk * 8 + tig]);
                    bb[1] = __float_as_uint(Ks[nt * 8 + gid][kk * 8 + tig + 4]);
                    mma_tf32(Sf[nt], Qa[kk], bb);
                }
            }

            // ---- online softmax on C-fragments (row = 4-lane group) ----
#pragma unroll
            for (int u = 0; u < 2; u++) {
                const int row = row0 + u * 8;
                float tmax = NEG_INF;
#pragma unroll
                for (int nt = 0; nt < 8; nt++)
#pragma unroll
                    for (int j = 0; j < 2; j++) {
                        const int col = k0 + nt * 8 + 2 * tig + j;
                        float s = Sf[nt][u * 2 + j];
                        if (col > row) s = NEG_INF;
                        Sf[nt][u * 2 + j] = s;
                        tmax = fmaxf(tmax, s);
                    }
                tmax = fmaxf(tmax, __shfl_xor_sync(0xffffffffu, tmax, 1));
                tmax = fmaxf(tmax, __shfl_xor_sync(0xffffffffu, tmax, 2));
                const float mn = fmaxf(m_[u], tmax);
                const float alpha = __expf(m_[u] - mn);
                float rsum = 0.f;
#pragma unroll
                for (int nt = 0; nt < 8; nt++)
#pragma unroll
                    for (int j = 0; j < 2; j++) {
                        const float p = __expf(Sf[nt][u * 2 + j] - mn);
                        Sf[nt][u * 2 + j] = p;
                        rsum += p;
                    }
                rsum += __shfl_xor_sync(0xffffffffu, rsum, 1);
                rsum += __shfl_xor_sync(0xffffffffu, rsum, 2);
                l_[u] = l_[u] * alpha + rsum;
                m_[u] = mn;
#pragma unroll
                for (int nt = 0; nt < 8; nt++)
#pragma unroll
                    for (int j = 0; j < 2; j++) Of[nt][u * 2 + j] *= alpha;
            }

            // ---- O += P @ V  (C-frag -> A-frag via shuffles, tf32) ----
#pragma unroll
            for (int kk = 0; kk < 8; kk++) {
                const int src = (lane & 28) | (tig >> 1);
                const int src2 = src + 2;
                const float e0 = __shfl_sync(0xffffffffu, Sf[kk][0], src);
                const float e1 = __shfl_sync(0xffffffffu, Sf[kk][1], src);
                const float e2 = __shfl_sync(0xffffffffu, Sf[kk][2], src);
                const float e3 = __shfl_sync(0xffffffffu, Sf[kk][3], src);
                const float f0 = __shfl_sync(0xffffffffu, Sf[kk][0], src2);
                const float f1 = __shfl_sync(0xffffffffu, Sf[kk][1], src2);
                const float f2 = __shfl_sync(0xffffffffu, Sf[kk][2], src2);
                const float f3 = __shfl_sync(0xffffffffu, Sf[kk][3], src2);
                const bool odd = tig & 1;
                uint32_t Pa[4];
                Pa[0] = tf32u(odd ? e1 : e0);
                Pa[1] = tf32u(odd ? e3 : e2);
                Pa[2] = tf32u(odd ? f1 : f0);
                Pa[3] = tf32u(odd ? f3 : f2);
#pragma unroll
                for (int nt = 0; nt < 8; nt++) {
                    uint32_t bb[2];
                    bb[0] = __float_as_uint(Vs[kk * 8 + tig][nt * 8 + gid]);
                    bb[1] = __float_as_uint(Vs[kk * 8 + tig + 4][nt * 8 + gid]);
                    mma_tf32(Of[nt], Pa, bb);
                }
            }
        }
        __syncthreads();
    }

    // ---- normalize + write heads-concatenated sa[b, n, h*64+d] ----
    const float inv0 = 1.f / l_[0];
    const float inv1 = 1.f / l_[1];
    float* dst = g_sa + ((size_t)(b * N_ + q0 + wid * 16 + gid)) * E_ + h * HD_;
#pragma unroll
    for (int nt = 0; nt < 8; nt++) {
        const int col = nt * 8 + 2 * tig;
        *(float2*)&dst[col] =
            make_float2(Of[nt][0] * inv0, Of[nt][1] * inv0);
        *(float2*)&dst[(size_t)8 * E_ + col] =
            make_float2(Of[nt][2] * inv1, Of[nt][3] * inv1);
    }
}

// ---------------------------------------------------------------------------
extern "C" void kernel_launch(void* const* d_in, const int* in_sizes, int n_in,
                              void* d_out, int out_size)
{
    const float* x = nullptr;
    const float* Wqkv = nullptr;
    const float* bqkv = nullptr;
    const float* Wout = nullptr;
    const float* bout = nullptr;
    for (int i = 0; i < n_in; i++) {
        switch (in_sizes[i]) {
            case B_ * N_ * E_:        x    = (const float*)d_in[i]; break; // 4194304
            case H_ * E_ * 3 * HD_:   Wqkv = (const float*)d_in[i]; break; // 3145728
            case H_ * 3 * HD_:        bqkv = (const float*)d_in[i]; break; // 3072
            case E_ * E_:             Wout = (const float*)d_in[i]; break; // 1048576
            case E_:                  bout = (const float*)d_in[i]; break; // 1024
            default: break;
        }
    }
    float* out = (float*)d_out;

    qkv_kernel<<<dim3(N_ / 128, 2, B_ * H_), 256>>>(x, Wqkv, bqkv);
    attn_kernel<<<dim3(N_ / 128, B_ * H_), 256>>>();
    outproj_kernel<<<dim3((B_ * N_) / 128, E_ / 128), 256>>>(Wout, bout, out);
}

// round 8
// speedup vs baseline: 5.9126x; 1.0292x over previous
#include <cuda_runtime.h>
#include <math.h>
#include <stdint.h>

#define B_  2
#define N_  2048
#define E_  1024
#define H_  16
#define HD_ 64

#define NEG_INF __int_as_float(0xff800000)

// Scratch (device globals — no runtime allocation allowed)
__device__ float g_q[(size_t)B_ * H_ * N_ * HD_];   // pre-scaled by 0.125, tf32-rounded
__device__ float g_k[(size_t)B_ * H_ * N_ * HD_];   // tf32-rounded
__device__ float g_v[(size_t)B_ * H_ * N_ * HD_];   // tf32-rounded
__device__ float g_sa[(size_t)B_ * N_ * E_];        // tf32-rounded
__device__ float g_xr[(size_t)B_ * N_ * E_];        // x, tf32-rounded
__device__ float g_wqkvR[(size_t)H_ * E_ * 192];    // Wqkv, tf32-rounded (same layout)
__device__ float g_woutR[(size_t)E_ * E_];          // Wout, tf32-rounded (same layout)

// ---------------------------------------------------------------------------
// helpers
// ---------------------------------------------------------------------------
__device__ __forceinline__ uint32_t tf32u(float x) {
    uint32_t u;
    asm("cvt.rna.tf32.f32 %0, %1;" : "=r"(u) : "f"(x));
    return u;
}
__device__ __forceinline__ float tf32f(float x) {
    return __uint_as_float(tf32u(x));
}
__device__ __forceinline__ float4 tf32f4(float4 v) {
    return make_float4(tf32f(v.x), tf32f(v.y), tf32f(v.z), tf32f(v.w));
}

__device__ __forceinline__ void mma_tf32(float (&d)[4], const uint32_t (&a)[4],
                                         const uint32_t (&b)[2]) {
    asm volatile(
        "mma.sync.aligned.m16n8k8.row.col.f32.tf32.tf32.f32 "
        "{%0,%1,%2,%3},{%4,%5,%6,%7},{%8,%9},{%0,%1,%2,%3};"
        : "+f"(d[0]), "+f"(d[1]), "+f"(d[2]), "+f"(d[3])
        : "r"(a[0]), "r"(a[1]), "r"(a[2]), "r"(a[3]), "r"(b[0]), "r"(b[1]));
}

__device__ __forceinline__ uint32_t smem_u32(const void* p) {
    uint32_t a;
    asm("{ .reg .u64 t; cvta.to.shared.u64 t, %1; cvt.u32.u64 %0, t; }"
        : "=r"(a) : "l"(p));
    return a;
}

__device__ __forceinline__ void cp16(uint32_t dst, const void* src) {
    asm volatile("cp.async.cg.shared.global [%0], [%1], 16;"
                 :: "r"(dst), "l"(src) : "memory");
}
#define CP_COMMIT() asm volatile("cp.async.commit_group;" ::: "memory")
#define CP_WAIT0()  asm volatile("cp.async.wait_group 0;" ::: "memory")
#define CP_WAIT1()  asm volatile("cp.async.wait_group 1;" ::: "memory")

// ---------------------------------------------------------------------------
// elementwise tf32 rounding prep
// ---------------------------------------------------------------------------
__global__ void round_k(const float4* __restrict__ src, float4* __restrict__ dst,
                        int n4) {
    int i = blockIdx.x * 256 + threadIdx.x;
    if (i < n4) dst[i] = tf32f4(src[i]);
}

// ---------------------------------------------------------------------------
// QKV: block = 128 tokens x 192 qkv-cols (fused), 8 warps 2m x 4n, warp 64x48.
// cp.async 2-stage pipeline. A smem pitch 36 (conflict-free), B pitch 200.
// Epilogue routes cols to K/Q/V, adds bias, pre-scales Q by 0.125, tf32-rounds.
// ---------------------------------------------------------------------------
#define QKV_STAGE_F  (128 * 36 + 32 * 200)     // 11008 floats
#define QKV_SMEM     (2 * QKV_STAGE_F * 4)     // 88064 bytes
__global__ __launch_bounds__(256) void qkv_kernel(const float* __restrict__ bqkv)
{
    extern __shared__ float sm[];
    const uint32_t sbase = smem_u32(sm);
    const int tid = threadIdx.x;
    const int lane = tid & 31, wid = tid >> 5;
    const int gid = lane >> 2, tig = lane & 3;
    const int wm = wid >> 2, wn = wid & 3;

    const int n0 = blockIdx.x << 7;
    const int bh = blockIdx.y;
    const int h = bh & 15, b = bh >> 4;

    const float* Asrc = g_xr + ((size_t)b * N_ + n0) * E_;
    const float* Bsrc = g_wqkvR + (size_t)h * E_ * 192;

    auto stage = [&](int ch, int s) {
        const uint32_t sa = sbase + (uint32_t)(s * QKV_STAGE_F * 4);
        const uint32_t sb = sa + 4608u * 4u;
        const int kc = ch * 32;
#pragma unroll
        for (int j = 0; j < 4; j++) {               // A: 1024 ops
            const int i = tid + j * 256;
            const int row = i >> 3, c4 = (i & 7) << 2;
            cp16(sa + (uint32_t)(row * 36 + c4) * 4,
                 Asrc + (size_t)row * E_ + kc + c4);
        }
#pragma unroll
        for (int j = 0; j < 6; j++) {               // B: 1536 ops
            const int i = tid + j * 256;
            const int row = i / 48, nq = (i % 48) << 2;
            cp16(sb + (uint32_t)(row * 200 + nq) * 4,
                 Bsrc + (size_t)(kc + row) * 192 + nq);
        }
    };

    float acc[4][6][4];
#pragma unroll
    for (int mt = 0; mt < 4; mt++)
#pragma unroll
        for (int nt = 0; nt < 6; nt++)
#pragma unroll
            for (int j = 0; j < 4; j++) acc[mt][nt][j] = 0.f;

    stage(0, 0); CP_COMMIT();
    stage(1, 1); CP_COMMIT();

    for (int ch = 0; ch < 32; ch++) {
        if (ch == 31) { CP_WAIT0(); } else { CP_WAIT1(); }
        __syncthreads();
        const float* sa = sm + (ch & 1) * QKV_STAGE_F;
        const float* sb = sa + 4608;
#pragma unroll
        for (int kk = 0; kk < 4; kk++) {
            uint32_t a[4][4], bf[6][2];
#pragma unroll
            for (int mt = 0; mt < 4; mt++) {
                const int rb = wm * 64 + mt * 16;
                a[mt][0] = __float_as_uint(sa[(rb + gid) * 36 + kk * 8 + tig]);
                a[mt][1] = __float_as_uint(sa[(rb + 8 + gid) * 36 + kk * 8 + tig]);
                a[mt][2] = __float_as_uint(sa[(rb + gid) * 36 + kk * 8 + tig + 4]);
                a[mt][3] = __float_as_uint(sa[(rb + 8 + gid) * 36 + kk * 8 + tig + 4]);
            }
#pragma unroll
            for (int nt = 0; nt < 6; nt++) {
                const int col = wn * 48 + nt * 8 + gid;
                bf[nt][0] = __float_as_uint(sb[(kk * 8 + tig) * 200 + col]);
                bf[nt][1] = __float_as_uint(sb[(kk * 8 + tig + 4) * 200 + col]);
            }
#pragma unroll
            for (int mt = 0; mt < 4; mt++)
#pragma unroll
                for (int nt = 0; nt < 6; nt++)
                    mma_tf32(acc[mt][nt], a[mt], bf[nt]);
        }
        __syncthreads();
        if (ch + 2 < 32) { stage(ch + 2, ch & 1); CP_COMMIT(); }
    }

    // epilogue: route to K/Q/V, bias, pre-scale Q, round
#pragma unroll
    for (int mt = 0; mt < 4; mt++) {
        const int row = wm * 64 + mt * 16 + gid;
#pragma unroll
        for (int nt = 0; nt < 6; nt++) {
            const int c = wn * 48 + nt * 8 + 2 * tig;
            const int part = c >> 6, cc = c & 63;
            float* base = (part == 0) ? g_k : (part == 1) ? g_q : g_v;
            const float sc = (part == 1) ? 0.125f : 1.f;
            const float b0 = bqkv[h * 192 + c], b1 = bqkv[h * 192 + c + 1];
            float* p = base + ((size_t)bh * N_ + n0 + row) * HD_ + cc;
            *(float2*)p = make_float2(tf32f((acc[mt][nt][0] + b0) * sc),
                                      tf32f((acc[mt][nt][1] + b1) * sc));
            *(float2*)(p + (size_t)8 * HD_) =
                make_float2(tf32f((acc[mt][nt][2] + b0) * sc),
                            tf32f((acc[mt][nt][3] + b1) * sc));
        }
    }
}

// ---------------------------------------------------------------------------
// Output projection: block 128 x 256, 8 warps 2m x 4n, warp 64x64.
// ---------------------------------------------------------------------------
#define OUT_STAGE_F  (128 * 36 + 32 * 264)     // 13056 floats
#define OUT_SMEM     (2 * OUT_STAGE_F * 4)     // 104448 bytes
__global__ __launch_bounds__(256) void outproj_kernel(
    const float* __restrict__ bout, float* __restrict__ out)
{
    extern __shared__ float sm[];
    const uint32_t sbase = smem_u32(sm);
    const int tid = threadIdx.x;
    const int lane = tid & 31, wid = tid >> 5;
    const int gid = lane >> 2, tig = lane & 3;
    const int wm = wid >> 2, wn = wid & 3;

    const int r0 = blockIdx.x << 7;
    const int c0 = blockIdx.y << 8;

    const float* Asrc = g_sa + (size_t)r0 * E_;
    const float* Bsrc = g_woutR + c0;

    auto stage = [&](int ch, int s) {
        const uint32_t sa = sbase + (uint32_t)(s * OUT_STAGE_F * 4);
        const uint32_t sb = sa + 4608u * 4u;
        const int kc = ch * 32;
#pragma unroll
        for (int j = 0; j < 4; j++) {               // A: 1024 ops
            const int i = tid + j * 256;
            const int row = i >> 3, c4 = (i & 7) << 2;
            cp16(sa + (uint32_t)(row * 36 + c4) * 4,
                 Asrc + (size_t)row * E_ + kc + c4);
        }
#pragma unroll
        for (int j = 0; j < 8; j++) {               // B: 2048 ops
            const int i = tid + j * 256;
            const int row = i >> 6, nq = (i & 63) << 2;
            cp16(sb + (uint32_t)(row * 264 + nq) * 4,
                 Bsrc + (size_t)(kc + row) * E_ + nq);
        }
    };

    float acc[4][8][4];
#pragma unroll
    for (int mt = 0; mt < 4; mt++)
#pragma unroll
        for (int nt = 0; nt < 8; nt++)
#pragma unroll
            for (int j = 0; j < 4; j++) acc[mt][nt][j] = 0.f;

    stage(0, 0); CP_COMMIT();
    stage(1, 1); CP_COMMIT();

    for (int ch = 0; ch < 32; ch++) {
        if (ch == 31) { CP_WAIT0(); } else { CP_WAIT1(); }
        __syncthreads();
        const float* sa = sm + (ch & 1) * OUT_STAGE_F;
        const float* sb = sa + 4608;
#pragma unroll
        for (int kk = 0; kk < 4; kk++) {
            uint32_t a[4][4], bf[8][2];
#pragma unroll
            for (int mt = 0; mt < 4; mt++) {
                const int rb = wm * 64 + mt * 16;
                a[mt][0] = __float_as_uint(sa[(rb + gid) * 36 + kk * 8 + tig]);
                a[mt][1] = __float_as_uint(sa[(rb + 8 + gid) * 36 + kk * 8 + tig]);
                a[mt][2] = __float_as_uint(sa[(rb + gid) * 36 + kk * 8 + tig + 4]);
                a[mt][3] = __float_as_uint(sa[(rb + 8 + gid) * 36 + kk * 8 + tig + 4]);
            }
#pragma unroll
            for (int nt = 0; nt < 8; nt++) {
                const int col = wn * 64 + nt * 8 + gid;
                bf[nt][0] = __float_as_uint(sb[(kk * 8 + tig) * 264 + col]);
                bf[nt][1] = __float_as_uint(sb[(kk * 8 + tig + 4) * 264 + col]);
            }
#pragma unroll
            for (int mt = 0; mt < 4; mt++)
#pragma unroll
                for (int nt = 0; nt < 8; nt++)
                    mma_tf32(acc[mt][nt], a[mt], bf[nt]);
        }
        __syncthreads();
        if (ch + 2 < 32) { stage(ch + 2, ch & 1); CP_COMMIT(); }
    }

#pragma unroll
    for (int mt = 0; mt < 4; mt++) {
        const int row = r0 + wm * 64 + mt * 16 + gid;
#pragma unroll
        for (int nt = 0; nt < 8; nt++) {
            const int col = c0 + wn * 64 + nt * 8 + 2 * tig;
            const float b0 = bout[col], b1 = bout[col + 1];
            *(float2*)&out[(size_t)row * E_ + col] =
                make_float2(acc[mt][nt][0] + b0, acc[mt][nt][1] + b1);
            *(float2*)&out[(size_t)(row + 8) * E_ + col] =
                make_float2(acc[mt][nt][2] + b0, acc[mt][nt][3] + b1);
        }
    }
}

// ---------------------------------------------------------------------------
// Flash attention: 4 warps, q-tile 128 (32 rows/warp), cp.async double-buffered
// K/V tiles (64 keys). Q fragments loaded directly from global (pre-scaled).
// ---------------------------------------------------------------------------
#define ATTN_TILE_F  (64 * 68)                 // 4352 floats per K or V tile
#define ATTN_SMEM    (2 * 2 * ATTN_TILE_F * 4) // 69632 bytes
__global__ __launch_bounds__(128, 2) void attn_kernel()
{
    extern __shared__ float sm[];
    const uint32_t sbase = smem_u32(sm);
    const int tid = threadIdx.x;
    const int lane = tid & 31, w = tid >> 5;
    const int gid = lane >> 2, tig = lane & 3;
    const int qt = (int)(gridDim.x - 1) - (int)blockIdx.x;   // heavy first
    const int bh = blockIdx.y;
    const int b = bh >> 4, h = bh & 15;
    const int q0 = qt << 7;

    const float* Kg = g_k + (size_t)bh * N_ * HD_;
    const float* Vg = g_v + (size_t)bh * N_ * HD_;

    // Q fragments straight from global (already 0.125-scaled + rounded)
    uint32_t Qa[8][2][4];
    {
        const float* Qw = g_q + ((size_t)bh * N_ + q0 + w * 32) * HD_;
#pragma unroll
        for (int kk = 0; kk < 8; kk++)
#pragma unroll
            for (int mt = 0; mt < 2; mt++) {
                const float* p = Qw + (size_t)(mt * 16 + gid) * HD_ + kk * 8 + tig;
                Qa[kk][mt][0] = __float_as_uint(p[0]);
                Qa[kk][mt][1] = __float_as_uint(p[8 * HD_]);
                Qa[kk][mt][2] = __float_as_uint(p[4]);
                Qa[kk][mt][3] = __float_as_uint(p[8 * HD_ + 4]);
            }
    }

    float m_[2][2] = {{NEG_INF, NEG_INF}, {NEG_INF, NEG_INF}};
    float l_[2][2] = {{0.f, 0.f}, {0.f, 0.f}};
    float Of[2][8][4];
#pragma unroll
    for (int mt = 0; mt < 2; mt++)
#pragma unroll
        for (int nt = 0; nt < 8; nt++)
#pragma unroll
            for (int j = 0; j < 4; j++) Of[mt][nt][j] = 0.f;

    const int wrow_max = q0 + w * 32 + 31;
    const int nkt = 2 * qt + 2;

    auto stage = [&](int kt) {
        const int s = kt & 1;
        const uint32_t ks = sbase + (uint32_t)(s * 2 * ATTN_TILE_F * 4);
        const uint32_t vs = ks + (uint32_t)(ATTN_TILE_F * 4);
        const int k0 = kt << 6;
#pragma unroll
        for (int j = 0; j < 8; j++) {               // 1024 ops each for K and V
            const int i = tid + j * 128;
            const int row = i >> 4, c4 = (i & 15) << 2;
            cp16(ks + (uint32_t)(row * 68 + c4) * 4,
                 Kg + (size_t)(k0 + row) * HD_ + c4);
            cp16(vs + (uint32_t)(row * 68 + c4) * 4,
                 Vg + (size_t)(k0 + row) * HD_ + c4);
        }
    };

    stage(0); CP_COMMIT();

    for (int kt = 0; kt < nkt; kt++) {
        if (kt + 1 < nkt) { stage(kt + 1); CP_COMMIT(); CP_WAIT1(); }
        else { CP_WAIT0(); }
        __syncthreads();
        const float* Ks = sm + (kt & 1) * 2 * ATTN_TILE_F;
        const float* Vs = Ks + ATTN_TILE_F;
        const int k0 = kt << 6;

        if (k0 <= wrow_max) {
            // ---- S = Q @ K^T ----
            float Sf[2][8][4];
#pragma unroll
            for (int mt = 0; mt < 2; mt++)
#pragma unroll
                for (int nt = 0; nt < 8; nt++)
#pragma unroll
                    for (int j = 0; j < 4; j++) Sf[mt][nt][j] = 0.f;

#pragma unroll
            for (int kk = 0; kk < 8; kk++)
#pragma unroll
                for (int nt = 0; nt < 8; nt++) {
                    uint32_t bb[2];
                    bb[0] = __float_as_uint(Ks[(nt * 8 + gid) * 68 + kk * 8 + tig]);
                    bb[1] = __float_as_uint(Ks[(nt * 8 + gid) * 68 + kk * 8 + tig + 4]);
                    mma_tf32(Sf[0][nt], Qa[kk][0], bb);
                    mma_tf32(Sf[1][nt], Qa[kk][1], bb);
                }

            // ---- online softmax (per mt, per 8-row half) ----
#pragma unroll
            for (int mt = 0; mt < 2; mt++)
#pragma unroll
                for (int u = 0; u < 2; u++) {
                    const int row = q0 + w * 32 + mt * 16 + u * 8 + gid;
                    float tmax = NEG_INF;
#pragma unroll
                    for (int nt = 0; nt < 8; nt++)
#pragma unroll
                        for (int j = 0; j < 2; j++) {
                            const int col = k0 + nt * 8 + 2 * tig + j;
                            float s = Sf[mt][nt][u * 2 + j];
                            if (col > row) s = NEG_INF;
                            Sf[mt][nt][u * 2 + j] = s;
                            tmax = fmaxf(tmax, s);
                        }
                    tmax = fmaxf(tmax, __shfl_xor_sync(0xffffffffu, tmax, 1));
                    tmax = fmaxf(tmax, __shfl_xor_sync(0xffffffffu, tmax, 2));
                    const float mn = fmaxf(m_[mt][u], tmax);
                    const float alpha = __expf(m_[mt][u] - mn);
                    float rsum = 0.f;
#pragma unroll
                    for (int nt = 0; nt < 8; nt++)
#pragma unroll
                        for (int j = 0; j < 2; j++) {
                            const float p = __expf(Sf[mt][nt][u * 2 + j] - mn);
                            Sf[mt][nt][u * 2 + j] = p;
                            rsum += p;
                        }
                    rsum += __shfl_xor_sync(0xffffffffu, rsum, 1);
                    rsum += __shfl_xor_sync(0xffffffffu, rsum, 2);
                    l_[mt][u] = l_[mt][u] * alpha + rsum;
                    m_[mt][u] = mn;
#pragma unroll
                    for (int nt = 0; nt < 8; nt++)
#pragma unroll
                        for (int j = 0; j < 2; j++) Of[mt][nt][u * 2 + j] *= alpha;
                }

            // ---- O += P @ V (C-frag -> A-frag via shuffles) ----
#pragma unroll
            for (int kk = 0; kk < 8; kk++) {
                const int src = (lane & 28) | (tig >> 1);
                const int src2 = src + 2;
                const bool odd = tig & 1;
                uint32_t Pa[2][4];
#pragma unroll
                for (int mt = 0; mt < 2; mt++) {
                    const float e0 = __shfl_sync(0xffffffffu, Sf[mt][kk][0], src);
                    const float e1 = __shfl_sync(0xffffffffu, Sf[mt][kk][1], src);
                    const float e2 = __shfl_sync(0xffffffffu, Sf[mt][kk][2], src);
                    const float e3 = __shfl_sync(0xffffffffu, Sf[mt][kk][3], src);
                    const float f0 = __shfl_sync(0xffffffffu, Sf[mt][kk][0], src2);
                    const float f1 = __shfl_sync(0xffffffffu, Sf[mt][kk][1], src2);
                    const float f2 = __shfl_sync(0xffffffffu, Sf[mt][kk][2], src2);
                    const float f3 = __shfl_sync(0xffffffffu, Sf[mt][kk][3], src2);
                    Pa[mt][0] = tf32u(odd ? e1 : e0);
                    Pa[mt][1] = tf32u(odd ? e3 : e2);
                    Pa[mt][2] = tf32u(odd ? f1 : f0);
                    Pa[mt][3] = tf32u(odd ? f3 : f2);
                }
#pragma unroll
                for (int nt = 0; nt < 8; nt++) {
                    uint32_t bb[2];
                    bb[0] = __float_as_uint(Vs[(kk * 8 + tig) * 68 + nt * 8 + gid]);
                    bb[1] = __float_as_uint(Vs[(kk * 8 + tig + 4) * 68 + nt * 8 + gid]);
                    mma_tf32(Of[0][nt], Pa[0], bb);
                    mma_tf32(Of[1][nt], Pa[1], bb);
                }
            }
        }
        __syncthreads();
    }

    // ---- normalize + write heads-concatenated sa[b, n, h*64+d] (rounded) ----
#pragma unroll
    for (int mt = 0; mt < 2; mt++)
#pragma unroll
        for (int u = 0; u < 2; u++) {
            const float inv = 1.f / l_[mt][u];
            float* dst = g_sa +
                ((size_t)(b * N_ + q0 + w * 32 + mt * 16 + u * 8 + gid)) * E_ +
                h * HD_;
#pragma unroll
            for (int nt = 0; nt < 8; nt++) {
                const int col = nt * 8 + 2 * tig;
                *(float2*)&dst[col] =
                    make_float2(tf32f(Of[mt][nt][u * 2] * inv),
                                tf32f(Of[mt][nt][u * 2 + 1] * inv));
            }
        }
}

// ---------------------------------------------------------------------------
extern "C" void kernel_launch(void* const* d_in, const int* in_sizes, int n_in,
                              void* d_out, int out_size)
{
    const float* x = nullptr;
    const float* Wqkv = nullptr;
    const float* bqkv = nullptr;
    const float* Wout = nullptr;
    const float* bout = nullptr;
    for (int i = 0; i < n_in; i++) {
        switch (in_sizes[i]) {
            case B_ * N_ * E_:        x    = (const float*)d_in[i]; break; // 4194304
            case H_ * E_ * 3 * HD_:   Wqkv = (const float*)d_in[i]; break; // 3145728
            case H_ * 3 * HD_:        bqkv = (const float*)d_in[i]; break; // 3072
            case E_ * E_:             Wout = (const float*)d_in[i]; break; // 1048576
            case E_:                  bout = (const float*)d_in[i]; break; // 1024
            default: break;
        }
    }
    float* out = (float*)d_out;

    cudaFuncSetAttribute(qkv_kernel, cudaFuncAttributeMaxDynamicSharedMemorySize,
                         QKV_SMEM);
    cudaFuncSetAttribute(outproj_kernel,
                         cudaFuncAttributeMaxDynamicSharedMemorySize, OUT_SMEM);
    cudaFuncSetAttribute(attn_kernel, cudaFuncAttributeMaxDynamicSharedMemorySize,
                         ATTN_SMEM);

    float* d_xr;    cudaGetSymbolAddress((void**)&d_xr, g_xr);
    float* d_wq;    cudaGetSymbolAddress((void**)&d_wq, g_wqkvR);
    float* d_wo;    cudaGetSymbolAddress((void**)&d_wo, g_woutR);

    round_k<<<4096, 256>>>((const float4*)x, (float4*)d_xr, 1048576);
    round_k<<<3072, 256>>>((const float4*)Wqkv, (float4*)d_wq, 786432);
    round_k<<<1024, 256>>>((const float4*)Wout, (float4*)d_wo, 262144);

    qkv_kernel<<<dim3(N_ / 128, B_ * H_), 256, QKV_SMEM>>>(bqkv);
    attn_kernel<<<dim3(N_ / 128, B_ * H_), 128, ATTN_SMEM>>>();
    outproj_kernel<<<dim3((B_ * N_) / 128, E_ / 256), 256, OUT_SMEM>>>(bout, out);
}

// round 9
// speedup vs baseline: 5.9925x; 1.0135x over previous
#include <cuda_runtime.h>
#include <math.h>
#include <stdint.h>

#define B_  2
#define N_  2048
#define E_  1024
#define H_  16
#define HD_ 64

#define NEG_INF __int_as_float(0xff800000)

// Scratch (device globals — no runtime allocation allowed)
__device__ float g_q[(size_t)B_ * H_ * N_ * HD_];   // pre-scaled by 0.125, tf32-rounded
__device__ float g_k[(size_t)B_ * H_ * N_ * HD_];   // tf32-rounded
__device__ float g_v[(size_t)B_ * H_ * N_ * HD_];   // tf32-rounded
__device__ float g_sa[(size_t)B_ * N_ * E_];        // tf32-rounded
__device__ float g_xr[(size_t)B_ * N_ * E_];        // x, tf32-rounded
__device__ float g_wqkvR[(size_t)H_ * E_ * 192];    // Wqkv, tf32-rounded (same layout)
__device__ float g_woutR[(size_t)E_ * E_];          // Wout, tf32-rounded (same layout)

// ---------------------------------------------------------------------------
// helpers
// ---------------------------------------------------------------------------
__device__ __forceinline__ uint32_t tf32u(float x) {
    uint32_t u;
    asm("cvt.rna.tf32.f32 %0, %1;" : "=r"(u) : "f"(x));
    return u;
}
__device__ __forceinline__ float tf32f(float x) {
    return __uint_as_float(tf32u(x));
}
__device__ __forceinline__ float4 tf32f4(float4 v) {
    return make_float4(tf32f(v.x), tf32f(v.y), tf32f(v.z), tf32f(v.w));
}

__device__ __forceinline__ void mma_tf32(float (&d)[4], const uint32_t (&a)[4],
                                         const uint32_t (&b)[2]) {
    asm volatile(
        "mma.sync.aligned.m16n8k8.row.col.f32.tf32.tf32.f32 "
        "{%0,%1,%2,%3},{%4,%5,%6,%7},{%8,%9},{%0,%1,%2,%3};"
        : "+f"(d[0]), "+f"(d[1]), "+f"(d[2]), "+f"(d[3])
        : "r"(a[0]), "r"(a[1]), "r"(a[2]), "r"(a[3]), "r"(b[0]), "r"(b[1]));
}

__device__ __forceinline__ uint32_t smem_u32(const void* p) {
    uint32_t a;
    asm("{ .reg .u64 t; cvta.to.shared.u64 t, %1; cvt.u32.u64 %0, t; }"
        : "=r"(a) : "l"(p));
    return a;
}

__device__ __forceinline__ void cp16(uint32_t dst, const void* src) {
    asm volatile("cp.async.cg.shared.global [%0], [%1], 16;"
                 :: "r"(dst), "l"(src) : "memory");
}
#define CP_COMMIT() asm volatile("cp.async.commit_group;" ::: "memory")
#define CP_WAIT0()  asm volatile("cp.async.wait_group 0;" ::: "memory")
#define CP_WAIT1()  asm volatile("cp.async.wait_group 1;" ::: "memory")

// ---------------------------------------------------------------------------
// elementwise tf32 rounding prep
// ---------------------------------------------------------------------------
__global__ void round_k(const float4* __restrict__ src, float4* __restrict__ dst,
                        int n4) {
    int i = blockIdx.x * 256 + threadIdx.x;
    if (i < n4) dst[i] = tf32f4(src[i]);
}

// ---------------------------------------------------------------------------
// QKV: block = 128 tokens x 192 qkv-cols (fused), 16 warps 4m x 4n, warp 32x48.
// cp.async 2-stage pipeline; A pitch 36, B pitch 200.
// ---------------------------------------------------------------------------
#define QKV_STAGE_F  (128 * 36 + 32 * 200)     // 11008 floats
#define QKV_SMEM     (2 * QKV_STAGE_F * 4)     // 88064 bytes
__global__ __launch_bounds__(512) void qkv_kernel(const float* __restrict__ bqkv)
{
    extern __shared__ float sm[];
    const uint32_t sbase = smem_u32(sm);
    const int tid = threadIdx.x;
    const int lane = tid & 31, wid = tid >> 5;
    const int gid = lane >> 2, tig = lane & 3;
    const int wm = wid >> 2, wn = wid & 3;

    const int n0 = blockIdx.x << 7;
    const int bh = blockIdx.y;
    const int h = bh & 15, b = bh >> 4;

    const float* Asrc = g_xr + ((size_t)b * N_ + n0) * E_;
    const float* Bsrc = g_wqkvR + (size_t)h * E_ * 192;

    auto stage = [&](int ch, int s) {
        const uint32_t sa = sbase + (uint32_t)(s * QKV_STAGE_F * 4);
        const uint32_t sb = sa + 4608u * 4u;
        const int kc = ch * 32;
#pragma unroll
        for (int j = 0; j < 2; j++) {               // A: 1024 ops
            const int i = tid + j * 512;
            const int row = i >> 3, c4 = (i & 7) << 2;
            cp16(sa + (uint32_t)(row * 36 + c4) * 4,
                 Asrc + (size_t)row * E_ + kc + c4);
        }
#pragma unroll
        for (int j = 0; j < 3; j++) {               // B: 1536 ops
            const int i = tid + j * 512;
            const int row = i / 48, nq = (i % 48) << 2;
            cp16(sb + (uint32_t)(row * 200 + nq) * 4,
                 Bsrc + (size_t)(kc + row) * 192 + nq);
        }
    };

    float acc[2][6][4];
#pragma unroll
    for (int mt = 0; mt < 2; mt++)
#pragma unroll
        for (int nt = 0; nt < 6; nt++)
#pragma unroll
            for (int j = 0; j < 4; j++) acc[mt][nt][j] = 0.f;

    stage(0, 0); CP_COMMIT();
    stage(1, 1); CP_COMMIT();

    for (int ch = 0; ch < 32; ch++) {
        if (ch == 31) { CP_WAIT0(); } else { CP_WAIT1(); }
        __syncthreads();
        const float* sa = sm + (ch & 1) * QKV_STAGE_F;
        const float* sb = sa + 4608;
#pragma unroll
        for (int kk = 0; kk < 4; kk++) {
            uint32_t a[2][4], bf[6][2];
#pragma unroll
            for (int mt = 0; mt < 2; mt++) {
                const int rb = wm * 32 + mt * 16;
                a[mt][0] = __float_as_uint(sa[(rb + gid) * 36 + kk * 8 + tig]);
                a[mt][1] = __float_as_uint(sa[(rb + 8 + gid) * 36 + kk * 8 + tig]);
                a[mt][2] = __float_as_uint(sa[(rb + gid) * 36 + kk * 8 + tig + 4]);
                a[mt][3] = __float_as_uint(sa[(rb + 8 + gid) * 36 + kk * 8 + tig + 4]);
            }
#pragma unroll
            for (int nt = 0; nt < 6; nt++) {
                const int col = wn * 48 + nt * 8 + gid;
                bf[nt][0] = __float_as_uint(sb[(kk * 8 + tig) * 200 + col]);
                bf[nt][1] = __float_as_uint(sb[(kk * 8 + tig + 4) * 200 + col]);
            }
#pragma unroll
            for (int mt = 0; mt < 2; mt++)
#pragma unroll
                for (int nt = 0; nt < 6; nt++)
                    mma_tf32(acc[mt][nt], a[mt], bf[nt]);
        }
        __syncthreads();
        if (ch + 2 < 32) { stage(ch + 2, ch & 1); CP_COMMIT(); }
    }

    // epilogue: route to K/Q/V, bias, pre-scale Q, round
#pragma unroll
    for (int mt = 0; mt < 2; mt++) {
        const int row = wm * 32 + mt * 16 + gid;
#pragma unroll
        for (int nt = 0; nt < 6; nt++) {
            const int c = wn * 48 + nt * 8 + 2 * tig;
            const int part = c >> 6, cc = c & 63;
            float* base = (part == 0) ? g_k : (part == 1) ? g_q : g_v;
            const float sc = (part == 1) ? 0.125f : 1.f;
            const float b0 = bqkv[h * 192 + c], b1 = bqkv[h * 192 + c + 1];
            float* p = base + ((size_t)bh * N_ + n0 + row) * HD_ + cc;
            *(float2*)p = make_float2(tf32f((acc[mt][nt][0] + b0) * sc),
                                      tf32f((acc[mt][nt][1] + b1) * sc));
            *(float2*)(p + (size_t)8 * HD_) =
                make_float2(tf32f((acc[mt][nt][2] + b0) * sc),
                            tf32f((acc[mt][nt][3] + b1) * sc));
        }
    }
}

// ---------------------------------------------------------------------------
// Output projection: block 128 x 256, 16 warps 4m x 4n, warp 32x64.
// ---------------------------------------------------------------------------
#define OUT_STAGE_F  (128 * 36 + 32 * 264)     // 13056 floats
#define OUT_SMEM     (2 * OUT_STAGE_F * 4)     // 104448 bytes
__global__ __launch_bounds__(512) void outproj_kernel(
    const float* __restrict__ bout, float* __restrict__ out)
{
    extern __shared__ float sm[];
    const uint32_t sbase = smem_u32(sm);
    const int tid = threadIdx.x;
    const int lane = tid & 31, wid = tid >> 5;
    const int gid = lane >> 2, tig = lane & 3;
    const int wm = wid >> 2, wn = wid & 3;

    const int r0 = blockIdx.x << 7;
    const int c0 = blockIdx.y << 8;

    const float* Asrc = g_sa + (size_t)r0 * E_;
    const float* Bsrc = g_woutR + c0;

    auto stage = [&](int ch, int s) {
        const uint32_t sa = sbase + (uint32_t)(s * OUT_STAGE_F * 4);
        const uint32_t sb = sa + 4608u * 4u;
        const int kc = ch * 32;
#pragma unroll
        for (int j = 0; j < 2; j++) {               // A: 1024 ops
            const int i = tid + j * 512;
            const int row = i >> 3, c4 = (i & 7) << 2;
            cp16(sa + (uint32_t)(row * 36 + c4) * 4,
                 Asrc + (size_t)row * E_ + kc + c4);
        }
#pragma unroll
        for (int j = 0; j < 4; j++) {               // B: 2048 ops
            const int i = tid + j * 512;
            const int row = i >> 6, nq = (i & 63) << 2;
            cp16(sb + (uint32_t)(row * 264 + nq) * 4,
                 Bsrc + (size_t)(kc + row) * E_ + nq);
        }
    };

    float acc[2][8][4];
#pragma unroll
    for (int mt = 0; mt < 2; mt++)
#pragma unroll
        for (int nt = 0; nt < 8; nt++)
#pragma unroll
            for (int j = 0; j < 4; j++) acc[mt][nt][j] = 0.f;

    stage(0, 0); CP_COMMIT();
    stage(1, 1); CP_COMMIT();

    for (int ch = 0; ch < 32; ch++) {
        if (ch == 31) { CP_WAIT0(); } else { CP_WAIT1(); }
        __syncthreads();
        const float* sa = sm + (ch & 1) * OUT_STAGE_F;
        const float* sb = sa + 4608;
#pragma unroll
        for (int kk = 0; kk < 4; kk++) {
            uint32_t a[2][4], bf[8][2];
#pragma unroll
            for (int mt = 0; mt < 2; mt++) {
                const int rb = wm * 32 + mt * 16;
                a[mt][0] = __float_as_uint(sa[(rb + gid) * 36 + kk * 8 + tig]);
                a[mt][1] = __float_as_uint(sa[(rb + 8 + gid) * 36 + kk * 8 + tig]);
                a[mt][2] = __float_as_uint(sa[(rb + gid) * 36 + kk * 8 + tig + 4]);
                a[mt][3] = __float_as_uint(sa[(rb + 8 + gid) * 36 + kk * 8 + tig + 4]);
            }
#pragma unroll
            for (int nt = 0; nt < 8; nt++) {
                const int col = wn * 64 + nt * 8 + gid;
                bf[nt][0] = __float_as_uint(sb[(kk * 8 + tig) * 264 + col]);
                bf[nt][1] = __float_as_uint(sb[(kk * 8 + tig + 4) * 264 + col]);
            }
#pragma unroll
            for (int mt = 0; mt < 2; mt++)
#pragma unroll
                for (int nt = 0; nt < 8; nt++)
                    mma_tf32(acc[mt][nt], a[mt], bf[nt]);
        }
        __syncthreads();
        if (ch + 2 < 32) { stage(ch + 2, ch & 1); CP_COMMIT(); }
    }

#pragma unroll
    for (int mt = 0; mt < 2; mt++) {
        const int row = r0 + wm * 32 + mt * 16 + gid;
#pragma unroll
        for (int nt = 0; nt < 8; nt++) {
            const int col = c0 + wn * 64 + nt * 8 + 2 * tig;
            const float b0 = bout[col], b1 = bout[col + 1];
            *(float2*)&out[(size_t)row * E_ + col] =
                make_float2(acc[mt][nt][0] + b0, acc[mt][nt][1] + b1);
            *(float2*)&out[(size_t)(row + 8) * E_ + col] =
                make_float2(acc[mt][nt][2] + b0, acc[mt][nt][3] + b1);
        }
    }
}

// ---------------------------------------------------------------------------
// Flash attention: 8 warps, q-tile 256 (32 rows/warp), cp.async double-buffered
// 64-key K/V tiles. Q fragments from global (pre-scaled + rounded).
// ---------------------------------------------------------------------------
#define ATTN_TILE_F  (64 * 68)                 // 4352 floats per K or V tile
#define ATTN_SMEM    (2 * 2 * ATTN_TILE_F * 4) // 69632 bytes
__global__ __launch_bounds__(256) void attn_kernel()
{
    extern __shared__ float sm[];
    const uint32_t sbase = smem_u32(sm);
    const int tid = threadIdx.x;
    const int lane = tid & 31, w = tid >> 5;
    const int gid = lane >> 2, tig = lane & 3;
    const int qt = (int)(gridDim.x - 1) - (int)blockIdx.x;   // heavy first
    const int bh = blockIdx.y;
    const int b = bh >> 4, h = bh & 15;
    const int q0 = qt << 8;

    const float* Kg = g_k + (size_t)bh * N_ * HD_;
    const float* Vg = g_v + (size_t)bh * N_ * HD_;

    // Q fragments straight from global (already 0.125-scaled + rounded)
    uint32_t Qa[8][2][4];
    {
        const float* Qw = g_q + ((size_t)bh * N_ + q0 + w * 32) * HD_;
#pragma unroll
        for (int kk = 0; kk < 8; kk++)
#pragma unroll
            for (int mt = 0; mt < 2; mt++) {
                const float* p = Qw + (size_t)(mt * 16 + gid) * HD_ + kk * 8 + tig;
                Qa[kk][mt][0] = __float_as_uint(p[0]);
                Qa[kk][mt][1] = __float_as_uint(p[8 * HD_]);
                Qa[kk][mt][2] = __float_as_uint(p[4]);
                Qa[kk][mt][3] = __float_as_uint(p[8 * HD_ + 4]);
            }
    }

    float m_[2][2] = {{NEG_INF, NEG_INF}, {NEG_INF, NEG_INF}};
    float l_[2][2] = {{0.f, 0.f}, {0.f, 0.f}};
    float Of[2][8][4];
#pragma unroll
    for (int mt = 0; mt < 2; mt++)
#pragma unroll
        for (int nt = 0; nt < 8; nt++)
#pragma unroll
            for (int j = 0; j < 4; j++) Of[mt][nt][j] = 0.f;

    const int wrow_max = q0 + w * 32 + 31;
    const int nkt = 4 * qt + 4;

    auto stage = [&](int kt) {
        const int s = kt & 1;
        const uint32_t ks = sbase + (uint32_t)(s * 2 * ATTN_TILE_F * 4);
        const uint32_t vs = ks + (uint32_t)(ATTN_TILE_F * 4);
        const int k0 = kt << 6;
#pragma unroll
        for (int j = 0; j < 4; j++) {               // 1024 ops each for K and V
            const int i = tid + j * 256;
            const int row = i >> 4, c4 = (i & 15) << 2;
            cp16(ks + (uint32_t)(row * 68 + c4) * 4,
                 Kg + (size_t)(k0 + row) * HD_ + c4);
            cp16(vs + (uint32_t)(row * 68 + c4) * 4,
                 Vg + (size_t)(k0 + row) * HD_ + c4);
        }
    };

    stage(0); CP_COMMIT();

    for (int kt = 0; kt < nkt; kt++) {
        if (kt + 1 < nkt) { stage(kt + 1); CP_COMMIT(); CP_WAIT1(); }
        else { CP_WAIT0(); }
        __syncthreads();
        const float* Ks = sm + (kt & 1) * 2 * ATTN_TILE_F;
        const float* Vs = Ks + ATTN_TILE_F;
        const int k0 = kt << 6;

        if (k0 <= wrow_max) {
            // ---- S = Q @ K^T ----
            float Sf[2][8][4];
#pragma unroll
            for (int mt = 0; mt < 2; mt++)
#pragma unroll
                for (int nt = 0; nt < 8; nt++)
#pragma unroll
                    for (int j = 0; j < 4; j++) Sf[mt][nt][j] = 0.f;

#pragma unroll
            for (int kk = 0; kk < 8; kk++)
#pragma unroll
                for (int nt = 0; nt < 8; nt++) {
                    uint32_t bb[2];
                    bb[0] = __float_as_uint(Ks[(nt * 8 + gid) * 68 + kk * 8 + tig]);
                    bb[1] = __float_as_uint(Ks[(nt * 8 + gid) * 68 + kk * 8 + tig + 4]);
                    mma_tf32(Sf[0][nt], Qa[kk][0], bb);
                    mma_tf32(Sf[1][nt], Qa[kk][1], bb);
                }

            // ---- online softmax (per mt, per 8-row half) ----
#pragma unroll
            for (int mt = 0; mt < 2; mt++)
#pragma unroll
                for (int u = 0; u < 2; u++) {
                    const int row = q0 + w * 32 + mt * 16 + u * 8 + gid;
                    float tmax = NEG_INF;
#pragma unroll
                    for (int nt = 0; nt < 8; nt++)
#pragma unroll
                        for (int j = 0; j < 2; j++) {
                            const int col = k0 + nt * 8 + 2 * tig + j;
                            float s = Sf[mt][nt][u * 2 + j];
                            if (col > row) s = NEG_INF;
                            Sf[mt][nt][u * 2 + j] = s;
                            tmax = fmaxf(tmax, s);
                        }
                    tmax = fmaxf(tmax, __shfl_xor_sync(0xffffffffu, tmax, 1));
                    tmax = fmaxf(tmax, __shfl_xor_sync(0xffffffffu, tmax, 2));
                    const float mn = fmaxf(m_[mt][u], tmax);
                    const float alpha = __expf(m_[mt][u] - mn);
                    float rsum = 0.f;
#pragma unroll
                    for (int nt = 0; nt < 8; nt++)
#pragma unroll
                        for (int j = 0; j < 2; j++) {
                            const float p = __expf(Sf[mt][nt][u * 2 + j] - mn);
                            Sf[mt][nt][u * 2 + j] = p;
                            rsum += p;
                        }
                    rsum += __shfl_xor_sync(0xffffffffu, rsum, 1);
                    rsum += __shfl_xor_sync(0xffffffffu, rsum, 2);
                    l_[mt][u] = l_[mt][u] * alpha + rsum;
                    m_[mt][u] = mn;
#pragma unroll
                    for (int nt = 0; nt < 8; nt++)
#pragma unroll
                        for (int j = 0; j < 2; j++) Of[mt][nt][u * 2 + j] *= alpha;
                }

            // ---- O += P @ V (C-frag -> A-frag via shuffles) ----
#pragma unroll
            for (int kk = 0; kk < 8; kk++) {
                const int src = (lane & 28) | (tig >> 1);
                const int src2 = src + 2;
                const bool odd = tig & 1;
                uint32_t Pa[2][4];
#pragma unroll
                for (int mt = 0; mt < 2; mt++) {
                    const float e0 = __shfl_sync(0xffffffffu, Sf[mt][kk][0], src);
                    const float e1 = __shfl_sync(0xffffffffu, Sf[mt][kk][1], src);
                    const float e2 = __shfl_sync(0xffffffffu, Sf[mt][kk][2], src);
                    const float e3 = __shfl_sync(0xffffffffu, Sf[mt][kk][3], src);
                    const float f0 = __shfl_sync(0xffffffffu, Sf[mt][kk][0], src2);
                    const float f1 = __shfl_sync(0xffffffffu, Sf[mt][kk][1], src2);
                    const float f2 = __shfl_sync(0xffffffffu, Sf[mt][kk][2], src2);
                    const float f3 = __shfl_sync(0xffffffffu, Sf[mt][kk][3], src2);
                    Pa[mt][0] = tf32u(odd ? e1 : e0);
                    Pa[mt][1] = tf32u(odd ? e3 : e2);
                    Pa[mt][2] = tf32u(odd ? f1 : f0);
                    Pa[mt][3] = tf32u(odd ? f3 : f2);
                }
#pragma unroll
                for (int nt = 0; nt < 8; nt++) {
                    uint32_t bb[2];
                    bb[0] = __float_as_uint(Vs[(kk * 8 + tig) * 68 + nt * 8 + gid]);
                    bb[1] = __float_as_uint(Vs[(kk * 8 + tig + 4) * 68 + nt * 8 + gid]);
                    mma_tf32(Of[0][nt], Pa[0], bb);
                    mma_tf32(Of[1][nt], Pa[1], bb);
                }
            }
        }
        __syncthreads();
    }

    // ---- normalize + write heads-concatenated sa[b, n, h*64+d] (rounded) ----
#pragma unroll
    for (int mt = 0; mt < 2; mt++)
#pragma unroll
        for (int u = 0; u < 2; u++) {
            const float inv = 1.f / l_[mt][u];
            float* dst = g_sa +
                ((size_t)(b * N_ + q0 + w * 32 + mt * 16 + u * 8 + gid)) * E_ +
                h * HD_;
#pragma unroll
            for (int nt = 0; nt < 8; nt++) {
                const int col = nt * 8 + 2 * tig;
                *(float2*)&dst[col] =
                    make_float2(tf32f(Of[mt][nt][u * 2] * inv),
                                tf32f(Of[mt][nt][u * 2 + 1] * inv));
            }
        }
}

// ---------------------------------------------------------------------------
extern "C" void kernel_launch(void* const* d_in, const int* in_sizes, int n_in,
                              void* d_out, int out_size)
{
    const float* x = nullptr;
    const float* Wqkv = nullptr;
    const float* bqkv = nullptr;
    const float* Wout = nullptr;
    const float* bout = nullptr;
    for (int i = 0; i < n_in; i++) {
        switch (in_sizes[i]) {
            case B_ * N_ * E_:        x    = (const float*)d_in[i]; break; // 4194304
            case H_ * E_ * 3 * HD_:   Wqkv = (const float*)d_in[i]; break; // 3145728
            case H_ * 3 * HD_:        bqkv = (const float*)d_in[i]; break; // 3072
            case E_ * E_:             Wout = (const float*)d_in[i]; break; // 1048576
            case E_:                  bout = (const float*)d_in[i]; break; // 1024
            default: break;
        }
    }
    float* out = (float*)d_out;

    cudaFuncSetAttribute(qkv_kernel, cudaFuncAttributeMaxDynamicSharedMemorySize,
                         QKV_SMEM);
    cudaFuncSetAttribute(outproj_kernel,
                         cudaFuncAttributeMaxDynamicSharedMemorySize, OUT_SMEM);
    cudaFuncSetAttribute(attn_kernel, cudaFuncAttributeMaxDynamicSharedMemorySize,
                         ATTN_SMEM);

    float* d_xr;    cudaGetSymbolAddress((void**)&d_xr, g_xr);
    float* d_wq;    cudaGetSymbolAddress((void**)&d_wq, g_wqkvR);
    float* d_wo;    cudaGetSymbolAddress((void**)&d_wo, g_woutR);

    round_k<<<4096, 256>>>((const float4*)x, (float4*)d_xr, 1048576);
    round_k<<<3072, 256>>>((const float4*)Wqkv, (float4*)d_wq, 786432);
    round_k<<<1024, 256>>>((const float4*)Wout, (float4*)d_wo, 262144);

    qkv_kernel<<<dim3(N_ / 128, B_ * H_), 512, QKV_SMEM>>>(bqkv);
    attn_kernel<<<dim3(N_ / 256, B_ * H_), 256, ATTN_SMEM>>>();
    outproj_kernel<<<dim3((B_ * N_) / 128, E_ / 256), 512, OUT_SMEM>>>(bout, out);
}

// round 10
// speedup vs baseline: 6.2381x; 1.0410x over previous
#include <cuda_runtime.h>
#include <cuda_fp16.h>
#include <math.h>
#include <stdint.h>

#define B_  2
#define N_  2048
#define E_  1024
#define H_  16
#define HD_ 64

#define NEG_INF __int_as_float(0xff800000)

// Scratch (device globals — no runtime allocation allowed)
__device__ __half g_qh[(size_t)B_ * H_ * N_ * HD_];   // pre-scaled by 0.125
__device__ __half g_kh[(size_t)B_ * H_ * N_ * HD_];
__device__ __half g_vh[(size_t)B_ * H_ * N_ * HD_];
__device__ __half g_sah[(size_t)B_ * N_ * E_];
__device__ __half g_xh[(size_t)B_ * N_ * E_];
__device__ __half g_wqkvT[(size_t)H_ * 192 * E_];     // [h][n=192][k=1024]
__device__ __half g_woutT[(size_t)E_ * E_];           // [n][k]

// ---------------------------------------------------------------------------
// helpers
// ---------------------------------------------------------------------------
__device__ __forceinline__ uint32_t packh2(float a, float b) {
    __half2 h = __floats2half2_rn(a, b);
    return *(uint32_t*)&h;
}

__device__ __forceinline__ void mma_f16(float (&d)[4], const uint32_t (&a)[4],
                                        uint32_t b0, uint32_t b1) {
    asm volatile(
        "mma.sync.aligned.m16n8k16.row.col.f32.f16.f16.f32 "
        "{%0,%1,%2,%3},{%4,%5,%6,%7},{%8,%9},{%0,%1,%2,%3};"
        : "+f"(d[0]), "+f"(d[1]), "+f"(d[2]), "+f"(d[3])
        : "r"(a[0]), "r"(a[1]), "r"(a[2]), "r"(a[3]), "r"(b0), "r"(b1));
}

__device__ __forceinline__ uint32_t smem_u32(const void* p) {
    uint32_t a;
    asm("{ .reg .u64 t; cvta.to.shared.u64 t, %1; cvt.u32.u64 %0, t; }"
        : "=r"(a) : "l"(p));
    return a;
}

__device__ __forceinline__ void cp16(uint32_t dst, const void* src) {
    asm volatile("cp.async.cg.shared.global [%0], [%1], 16;"
                 :: "r"(dst), "l"(src) : "memory");
}
#define CP_COMMIT() asm volatile("cp.async.commit_group;" ::: "memory")
#define CP_WAIT0()  asm volatile("cp.async.wait_group 0;" ::: "memory")
#define CP_WAIT1()  asm volatile("cp.async.wait_group 1;" ::: "memory")

__device__ __forceinline__ void ldsm_x4_trans(uint32_t& d0, uint32_t& d1,
                                              uint32_t& d2, uint32_t& d3,
                                              uint32_t addr) {
    asm volatile(
        "ldmatrix.sync.aligned.m8n8.x4.trans.shared.b16 {%0,%1,%2,%3}, [%4];"
        : "=r"(d0), "=r"(d1), "=r"(d2), "=r"(d3) : "r"(addr));
}

// ---------------------------------------------------------------------------
// prep: x -> half; weights -> transposed half
// ---------------------------------------------------------------------------
__global__ void cvt_x(const float4* __restrict__ src, __half* __restrict__ dst,
                      int n4) {
    int i = blockIdx.x * 256 + threadIdx.x;
    if (i < n4) {
        float4 v = src[i];
        uint32_t* d = (uint32_t*)(dst + (size_t)i * 4);
        d[0] = packh2(v.x, v.y);
        d[1] = packh2(v.z, v.w);
    }
}

__global__ void prep_wqkvT(const float* __restrict__ W) {
    __shared__ float t[32][33];
    const int h = blockIdx.z;
    const int k0 = blockIdx.x << 5, n0 = blockIdx.y << 5;
    const int x = threadIdx.x, y0 = threadIdx.y;
#pragma unroll
    for (int yy = 0; yy < 32; yy += 8)
        t[y0 + yy][x] = W[(size_t)h * E_ * 192 + (size_t)(k0 + y0 + yy) * 192 +
                          n0 + x];
    __syncthreads();
#pragma unroll
    for (int yy = 0; yy < 32; yy += 8)
        g_wqkvT[(size_t)h * 192 * E_ + (size_t)(n0 + y0 + yy) * E_ + k0 + x] =
            __float2half_rn(t[x][y0 + yy]);
}

__global__ void prep_woutT(const float* __restrict__ W) {
    __shared__ float t[32][33];
    const int k0 = blockIdx.x << 5, n0 = blockIdx.y << 5;
    const int x = threadIdx.x, y0 = threadIdx.y;
#pragma unroll
    for (int yy = 0; yy < 32; yy += 8)
        t[y0 + yy][x] = W[(size_t)(k0 + y0 + yy) * E_ + n0 + x];
    __syncthreads();
#pragma unroll
    for (int yy = 0; yy < 32; yy += 8)
        g_woutT[(size_t)(n0 + y0 + yy) * E_ + k0 + x] =
            __float2half_rn(t[x][y0 + yy]);
}

// ---------------------------------------------------------------------------
// QKV: block 128 tokens x 192 cols, 16 warps 4m x 4n, warp 32x48, fp16 k16 mma.
// A smem [128][40]h, B smem [192][40]h (B = W^T, n-major), 2-stage cp.async.
// ---------------------------------------------------------------------------
#define QKV_STAGE_H (128 * 40 + 192 * 40)   // 12800 halves
#define QKV_SMEM    (2 * QKV_STAGE_H * 2)   // 51200 bytes
__global__ __launch_bounds__(512) void qkv_kernel(const float* __restrict__ bqkv)
{
    extern __shared__ __half smh[];
    const uint32_t sbase = smem_u32(smh);
    const int tid = threadIdx.x;
    const int lane = tid & 31, wid = tid >> 5;
    const int gid = lane >> 2, tig = lane & 3;
    const int wm = wid >> 2, wn = wid & 3;

    const int n0 = blockIdx.x << 7;
    const int bh = blockIdx.y;
    const int h = bh & 15, b = bh >> 4;

    const __half* Asrc = g_xh + ((size_t)b * N_ + n0) * E_;
    const __half* Bsrc = g_wqkvT + (size_t)h * 192 * E_;

    auto stage = [&](int ch, int s) {
        const uint32_t sa = sbase + (uint32_t)(s * QKV_STAGE_H * 2);
        const uint32_t sb = sa + 5120u * 2u;
        const int kc = ch * 32;
        {   // A: 128 rows x 4 groups = 512 ops
            const int row = tid >> 2, g8 = (tid & 3) << 3;
            cp16(sa + (uint32_t)(row * 40 + g8) * 2,
                 Asrc + (size_t)row * E_ + kc + g8);
        }
#pragma unroll
        for (int j = 0; j < 2; j++) {       // B: 192 x 4 = 768 ops
            const int i = tid + j * 512;
            if (i < 768) {
                const int row = i >> 2, g8 = (i & 3) << 3;
                cp16(sb + (uint32_t)(row * 40 + g8) * 2,
                     Bsrc + (size_t)row * E_ + kc + g8);
            }
        }
    };

    float acc[2][6][4];
#pragma unroll
    for (int mt = 0; mt < 2; mt++)
#pragma unroll
        for (int nt = 0; nt < 6; nt++)
#pragma unroll
            for (int j = 0; j < 4; j++) acc[mt][nt][j] = 0.f;

    stage(0, 0); CP_COMMIT();
    stage(1, 1); CP_COMMIT();

    for (int ch = 0; ch < 32; ch++) {
        if (ch == 31) { CP_WAIT0(); } else { CP_WAIT1(); }
        __syncthreads();
        const __half* sa = smh + (ch & 1) * QKV_STAGE_H;
        const __half* sb = sa + 5120;
#pragma unroll
        for (int ks = 0; ks < 2; ks++) {
            uint32_t a[2][4], bf[6][2];
#pragma unroll
            for (int mt = 0; mt < 2; mt++) {
                const __half* ap =
                    sa + (wm * 32 + mt * 16 + gid) * 40 + ks * 16 + 2 * tig;
                a[mt][0] = *(const uint32_t*)ap;
                a[mt][1] = *(const uint32_t*)(ap + 8 * 40);
                a[mt][2] = *(const uint32_t*)(ap + 8);
                a[mt][3] = *(const uint32_t*)(ap + 8 * 40 + 8);
            }
#pragma unroll
            for (int nt = 0; nt < 6; nt++) {
                const __half* bp =
                    sb + (wn * 48 + nt * 8 + gid) * 40 + ks * 16 + 2 * tig;
                bf[nt][0] = *(const uint32_t*)bp;
                bf[nt][1] = *(const uint32_t*)(bp + 8);
            }
#pragma unroll
            for (int mt = 0; mt < 2; mt++)
#pragma unroll
                for (int nt = 0; nt < 6; nt++)
                    mma_f16(acc[mt][nt], a[mt], bf[nt][0], bf[nt][1]);
        }
        __syncthreads();
        if (ch + 2 < 32) { stage(ch + 2, ch & 1); CP_COMMIT(); }
    }

    // epilogue: route to K/Q/V, bias, pre-scale Q, store half2
#pragma unroll
    for (int mt = 0; mt < 2; mt++) {
        const int row = wm * 32 + mt * 16 + gid;
#pragma unroll
        for (int nt = 0; nt < 6; nt++) {
            const int c = wn * 48 + nt * 8 + 2 * tig;
            const int part = c >> 6, cc = c & 63;
            __half* base = (part == 0) ? g_kh : (part == 1) ? g_qh : g_vh;
            const float sc = (part == 1) ? 0.125f : 1.f;
            const float b0 = bqkv[h * 192 + c], b1 = bqkv[h * 192 + c + 1];
            __half* p = base + ((size_t)bh * N_ + n0 + row) * HD_ + cc;
            *(uint32_t*)p = packh2((acc[mt][nt][0] + b0) * sc,
                                   (acc[mt][nt][1] + b1) * sc);
            *(uint32_t*)(p + (size_t)8 * HD_) =
                packh2((acc[mt][nt][2] + b0) * sc, (acc[mt][nt][3] + b1) * sc);
        }
    }
}

// ---------------------------------------------------------------------------
// Output projection: block 128 x 256, 16 warps 4m x 4n, warp 32x64, fp16 mma.
// ---------------------------------------------------------------------------
#define OUT_STAGE_H (128 * 40 + 256 * 40)   // 15360 halves
#define OUT_SMEM    (2 * OUT_STAGE_H * 2)   // 61440 bytes
__global__ __launch_bounds__(512) void outproj_kernel(
    const float* __restrict__ bout, float* __restrict__ out)
{
    extern __shared__ __half smh[];
    const uint32_t sbase = smem_u32(smh);
    const int tid = threadIdx.x;
    const int lane = tid & 31, wid = tid >> 5;
    const int gid = lane >> 2, tig = lane & 3;
    const int wm = wid >> 2, wn = wid & 3;

    const int r0 = blockIdx.x << 7;
    const int c0 = blockIdx.y << 8;

    const __half* Asrc = g_sah + (size_t)r0 * E_;
    const __half* Bsrc = g_woutT + (size_t)c0 * E_;

    auto stage = [&](int ch, int s) {
        const uint32_t sa = sbase + (uint32_t)(s * OUT_STAGE_H * 2);
        const uint32_t sb = sa + 5120u * 2u;
        const int kc = ch * 32;
        {
            const int row = tid >> 2, g8 = (tid & 3) << 3;
            cp16(sa + (uint32_t)(row * 40 + g8) * 2,
                 Asrc + (size_t)row * E_ + kc + g8);
        }
#pragma unroll
        for (int j = 0; j < 2; j++) {       // B: 256 x 4 = 1024 ops
            const int i = tid + j * 512;
            const int row = i >> 2, g8 = (i & 3) << 3;
            cp16(sb + (uint32_t)(row * 40 + g8) * 2,
                 Bsrc + (size_t)row * E_ + kc + g8);
        }
    };

    float acc[2][8][4];
#pragma unroll
    for (int mt = 0; mt < 2; mt++)
#pragma unroll
        for (int nt = 0; nt < 8; nt++)
#pragma unroll
            for (int j = 0; j < 4; j++) acc[mt][nt][j] = 0.f;

    stage(0, 0); CP_COMMIT();
    stage(1, 1); CP_COMMIT();

    for (int ch = 0; ch < 32; ch++) {
        if (ch == 31) { CP_WAIT0(); } else { CP_WAIT1(); }
        __syncthreads();
        const __half* sa = smh + (ch & 1) * OUT_STAGE_H;
        const __half* sb = sa + 5120;
#pragma unroll
        for (int ks = 0; ks < 2; ks++) {
            uint32_t a[2][4], bf[8][2];
#pragma unroll
            for (int mt = 0; mt < 2; mt++) {
                const __half* ap =
                    sa + (wm * 32 + mt * 16 + gid) * 40 + ks * 16 + 2 * tig;
                a[mt][0] = *(const uint32_t*)ap;
                a[mt][1] = *(const uint32_t*)(ap + 8 * 40);
                a[mt][2] = *(const uint32_t*)(ap + 8);
                a[mt][3] = *(const uint32_t*)(ap + 8 * 40 + 8);
            }
#pragma unroll
            for (int nt = 0; nt < 8; nt++) {
                const __half* bp =
                    sb + (wn * 64 + nt * 8 + gid) * 40 + ks * 16 + 2 * tig;
                bf[nt][0] = *(const uint32_t*)bp;
                bf[nt][1] = *(const uint32_t*)(bp + 8);
            }
#pragma unroll
            for (int mt = 0; mt < 2; mt++)
#pragma unroll
                for (int nt = 0; nt < 8; nt++)
                    mma_f16(acc[mt][nt], a[mt], bf[nt][0], bf[nt][1]);
        }
        __syncthreads();
        if (ch + 2 < 32) { stage(ch + 2, ch & 1); CP_COMMIT(); }
    }

#pragma unroll
    for (int mt = 0; mt < 2; mt++) {
        const int row = r0 + wm * 32 + mt * 16 + gid;
#pragma unroll
        for (int nt = 0; nt < 8; nt++) {
            const int col = c0 + wn * 64 + nt * 8 + 2 * tig;
            const float b0 = bout[col], b1 = bout[col + 1];
            *(float2*)&out[(size_t)row * E_ + col] =
                make_float2(acc[mt][nt][0] + b0, acc[mt][nt][1] + b1);
            *(float2*)&out[(size_t)(row + 8) * E_ + col] =
                make_float2(acc[mt][nt][2] + b0, acc[mt][nt][3] + b1);
        }
    }
}

// ---------------------------------------------------------------------------
// Flash attention, fp16 mma: 8 warps, q-tile 256 (32 rows/warp).
// K frags: direct half2 LDS (pitch 72). V frags: ldmatrix.x4.trans.
// P C-frag == fp16 A-frag layout -> pure register packs, no shuffles.
// ---------------------------------------------------------------------------
#define ATTN_TILE_H  (64 * 72)                  // 4608 halves / tile
#define ATTN_SMEM    (4 * ATTN_TILE_H * 2)      // 36864 bytes
__global__ __launch_bounds__(256) void attn_kernel()
{
    extern __shared__ __half smh[];
    const uint32_t sbase = smem_u32(smh);
    const int tid = threadIdx.x;
    const int lane = tid & 31, w = tid >> 5;
    const int gid = lane >> 2, tig = lane & 3;
    const int qt = (int)(gridDim.x - 1) - (int)blockIdx.x;   // heavy first
    const int bh = blockIdx.y;
    const int b = bh >> 4, h = bh & 15;
    const int q0 = qt << 8;

    const __half* Kg = g_kh + (size_t)bh * N_ * HD_;
    const __half* Vg = g_vh + (size_t)bh * N_ * HD_;

    // Q fragments from global (pre-scaled + half)
    uint32_t Qa[4][2][4];
    {
        const __half* Qw = g_qh + ((size_t)bh * N_ + q0 + w * 32) * HD_;
#pragma unroll
        for (int kk = 0; kk < 4; kk++)
#pragma unroll
            for (int mt = 0; mt < 2; mt++) {
                const __half* p =
                    Qw + (size_t)(mt * 16 + gid) * HD_ + kk * 16 + 2 * tig;
                Qa[kk][mt][0] = *(const uint32_t*)p;
                Qa[kk][mt][1] = *(const uint32_t*)(p + 8 * HD_);
                Qa[kk][mt][2] = *(const uint32_t*)(p + 8);
                Qa[kk][mt][3] = *(const uint32_t*)(p + 8 * HD_ + 8);
            }
    }

    float m_[2][2] = {{NEG_INF, NEG_INF}, {NEG_INF, NEG_INF}};
    float l_[2][2] = {{0.f, 0.f}, {0.f, 0.f}};
    float Of[2][8][4];
#pragma unroll
    for (int mt = 0; mt < 2; mt++)
#pragma unroll
        for (int nt = 0; nt < 8; nt++)
#pragma unroll
            for (int j = 0; j < 4; j++) Of[mt][nt][j] = 0.f;

    const int wrow_max = q0 + w * 32 + 31;
    const int nkt = 4 * qt + 4;

    auto stage = [&](int kt) {
        const int s = kt & 1;
        const uint32_t ks = sbase + (uint32_t)(s * 2 * ATTN_TILE_H * 2);
        const uint32_t vs = ks + (uint32_t)(ATTN_TILE_H * 2);
        const int k0 = kt << 6;
#pragma unroll
        for (int j = 0; j < 2; j++) {   // 512 ops each for K and V
            const int i = tid + j * 256;
            const int row = i >> 3, g8 = (i & 7) << 3;
            cp16(ks + (uint32_t)(row * 72 + g8) * 2,
                 Kg + (size_t)(k0 + row) * HD_ + g8);
            cp16(vs + (uint32_t)(row * 72 + g8) * 2,
                 Vg + (size_t)(k0 + row) * HD_ + g8);
        }
    };

    stage(0); CP_COMMIT();

    for (int kt = 0; kt < nkt; kt++) {
        if (kt + 1 < nkt) { stage(kt + 1); CP_COMMIT(); CP_WAIT1(); }
        else { CP_WAIT0(); }
        __syncthreads();
        const __half* Ks = smh + (kt & 1) * 2 * ATTN_TILE_H;
        const uint32_t vs_u32 =
            sbase + (uint32_t)((kt & 1) * 2 * ATTN_TILE_H + ATTN_TILE_H) * 2;
        const int k0 = kt << 6;

        if (k0 <= wrow_max) {
            // ---- S = Q @ K^T ----
            float Sf[2][8][4];
#pragma unroll
            for (int mt = 0; mt < 2; mt++)
#pragma unroll
                for (int nt = 0; nt < 8; nt++)
#pragma unroll
                    for (int j = 0; j < 4; j++) Sf[mt][nt][j] = 0.f;

#pragma unroll
            for (int kk = 0; kk < 4; kk++)
#pragma unroll
                for (int nt = 0; nt < 8; nt++) {
                    const __half* bp =
                        Ks + (nt * 8 + gid) * 72 + kk * 16 + 2 * tig;
                    const uint32_t b0 = *(const uint32_t*)bp;
                    const uint32_t b1 = *(const uint32_t*)(bp + 8);
                    mma_f16(Sf[0][nt], Qa[kk][0], b0, b1);
                    mma_f16(Sf[1][nt], Qa[kk][1], b0, b1);
                }

            // ---- online softmax ----
#pragma unroll
            for (int mt = 0; mt < 2; mt++)
#pragma unroll
                for (int u = 0; u < 2; u++) {
                    const int row = q0 + w * 32 + mt * 16 + u * 8 + gid;
                    float tmax = NEG_INF;
#pragma unroll
                    for (int nt = 0; nt < 8; nt++)
#pragma unroll
                        for (int j = 0; j < 2; j++) {
                            const int col = k0 + nt * 8 + 2 * tig + j;
                            float s = Sf[mt][nt][u * 2 + j];
                            if (col > row) s = NEG_INF;
                            Sf[mt][nt][u * 2 + j] = s;
                            tmax = fmaxf(tmax, s);
                        }
                    tmax = fmaxf(tmax, __shfl_xor_sync(0xffffffffu, tmax, 1));
                    tmax = fmaxf(tmax, __shfl_xor_sync(0xffffffffu, tmax, 2));
                    const float mn = fmaxf(m_[mt][u], tmax);
                    const float alpha = __expf(m_[mt][u] - mn);
                    float rsum = 0.f;
#pragma unroll
                    for (int nt = 0; nt < 8; nt++)
#pragma unroll
                        for (int j = 0; j < 2; j++) {
                            const float p = __expf(Sf[mt][nt][u * 2 + j] - mn);
                            Sf[mt][nt][u * 2 + j] = p;
                            rsum += p;
                        }
                    rsum += __shfl_xor_sync(0xffffffffu, rsum, 1);
                    rsum += __shfl_xor_sync(0xffffffffu, rsum, 2);
                    l_[mt][u] = l_[mt][u] * alpha + rsum;
                    m_[mt][u] = mn;
#pragma unroll
                    for (int nt = 0; nt < 8; nt++)
#pragma unroll
                        for (int j = 0; j < 2; j++)
                            Of[mt][nt][u * 2 + j] *= alpha;
                }

            // ---- O += P @ V : P packs to A-frags directly; V via ldmatrix ----
#pragma unroll
            for (int kk = 0; kk < 4; kk++) {
                uint32_t Pa[2][4];
#pragma unroll
                for (int mt = 0; mt < 2; mt++) {
                    Pa[mt][0] = packh2(Sf[mt][2 * kk][0], Sf[mt][2 * kk][1]);
                    Pa[mt][1] = packh2(Sf[mt][2 * kk][2], Sf[mt][2 * kk][3]);
                    Pa[mt][2] = packh2(Sf[mt][2 * kk + 1][0], Sf[mt][2 * kk + 1][1]);
                    Pa[mt][3] = packh2(Sf[mt][2 * kk + 1][2], Sf[mt][2 * kk + 1][3]);
                }
#pragma unroll
                for (int j = 0; j < 4; j++) {
                    const int vrow = kk * 16 + (lane & 15);
                    const int vcol = j * 16 + ((lane >> 4) << 3);
                    uint32_t d0, d1, d2, d3;
                    ldsm_x4_trans(d0, d1, d2, d3,
                                  vs_u32 + (uint32_t)(vrow * 72 + vcol) * 2);
                    mma_f16(Of[0][2 * j], Pa[0], d0, d1);
                    mma_f16(Of[1][2 * j], Pa[1], d0, d1);
                    mma_f16(Of[0][2 * j + 1], Pa[0], d2, d3);
                    mma_f16(Of[1][2 * j + 1], Pa[1], d2, d3);
                }
            }
        }
        __syncthreads();
    }

    // ---- normalize + write heads-concatenated sa[b, n, h*64+d] (half) ----
#pragma unroll
    for (int mt = 0; mt < 2; mt++)
#pragma unroll
        for (int u = 0; u < 2; u++) {
            const float inv = 1.f / l_[mt][u];
            __half* dst = g_sah +
                ((size_t)(b * N_ + q0 + w * 32 + mt * 16 + u * 8 + gid)) * E_ +
                h * HD_;
#pragma unroll
            for (int nt = 0; nt < 8; nt++) {
                const int col = nt * 8 + 2 * tig;
                *(uint32_t*)&dst[col] = packh2(Of[mt][nt][u * 2] * inv,
                                               Of[mt][nt][u * 2 + 1] * inv);
            }
        }
}

// ---------------------------------------------------------------------------
extern "C" void kernel_launch(void* const* d_in, const int* in_sizes, int n_in,
                              void* d_out, int out_size)
{
    const float* x = nullptr;
    const float* Wqkv = nullptr;
    const float* bqkv = nullptr;
    const float* Wout = nullptr;
    const float* bout = nullptr;
    for (int i = 0; i < n_in; i++) {
        switch (in_sizes[i]) {
            case B_ * N_ * E_:        x    = (const float*)d_in[i]; break; // 4194304
            case H_ * E_ * 3 * HD_:   Wqkv = (const float*)d_in[i]; break; // 3145728
            case H_ * 3 * HD_:        bqkv = (const float*)d_in[i]; break; // 3072
            case E_ * E_:             Wout = (const float*)d_in[i]; break; // 1048576
            case E_:                  bout = (const float*)d_in[i]; break; // 1024
            default: break;
        }
    }
    float* out = (float*)d_out;

    cudaFuncSetAttribute(qkv_kernel, cudaFuncAttributeMaxDynamicSharedMemorySize,
                         QKV_SMEM);
    cudaFuncSetAttribute(outproj_kernel,
                         cudaFuncAttributeMaxDynamicSharedMemorySize, OUT_SMEM);
    cudaFuncSetAttribute(attn_kernel, cudaFuncAttributeMaxDynamicSharedMemorySize,
                         ATTN_SMEM);

    __half* d_xh;
    cudaGetSymbolAddress((void**)&d_xh, g_xh);

    cvt_x<<<4096, 256>>>((const float4*)x, d_xh, 1048576);
    prep_wqkvT<<<dim3(32, 6, 16), dim3(32, 8)>>>(Wqkv);
    prep_woutT<<<dim3(32, 32), dim3(32, 8)>>>(Wout);

    qkv_kernel<<<dim3(N_ / 128, B_ * H_), 512, QKV_SMEM>>>(bqkv);
    attn_kernel<<<dim3(N_ / 256, B_ * H_), 256, ATTN_SMEM>>>();
    outproj_kernel<<<dim3((B_ * N_) / 128, E_ / 256), 512, OUT_SMEM>>>(bout, out);
}

// round 14
// speedup vs baseline: 10.1993x; 1.6350x over previous
#include <cuda_runtime.h>
#include <cuda_fp16.h>
#include <math.h>
#include <stdint.h>

#define B_  2
#define N_  2048
#define E_  1024
#define H_  16
#define HD_ 64

#define NEG_INF __int_as_float(0xff800000)

// Scratch (device globals — no runtime allocation allowed)
__device__ __half g_qh[(size_t)B_ * H_ * N_ * HD_];   // pre-scaled by 0.125
__device__ __half g_kh[(size_t)B_ * H_ * N_ * HD_];
__device__ __half g_vh[(size_t)B_ * H_ * N_ * HD_];
__device__ __half g_sah[(size_t)B_ * N_ * E_];
__device__ __half g_xh[(size_t)B_ * N_ * E_];
__device__ __half g_wqkvT[(size_t)H_ * 192 * E_];     // [h][n=192][k=1024]
__device__ __half g_woutT[(size_t)E_ * E_];           // [n][k]

// ---------------------------------------------------------------------------
// helpers
// ---------------------------------------------------------------------------
__device__ __forceinline__ uint32_t packh2(float a, float b) {
    __half2 h = __floats2half2_rn(a, b);
    return *(uint32_t*)&h;
}

__device__ __forceinline__ void mma_f16(float (&d)[4], const uint32_t (&a)[4],
                                        uint32_t b0, uint32_t b1) {
    asm volatile(
        "mma.sync.aligned.m16n8k16.row.col.f32.f16.f16.f32 "
        "{%0,%1,%2,%3},{%4,%5,%6,%7},{%8,%9},{%0,%1,%2,%3};"
        : "+f"(d[0]), "+f"(d[1]), "+f"(d[2]), "+f"(d[3])
        : "r"(a[0]), "r"(a[1]), "r"(a[2]), "r"(a[3]), "r"(b0), "r"(b1));
}

__device__ __forceinline__ uint32_t smem_u32(const void* p) {
    uint32_t a;
    asm("{ .reg .u64 t; cvta.to.shared.u64 t, %1; cvt.u32.u64 %0, t; }"
        : "=r"(a) : "l"(p));
    return a;
}

__device__ __forceinline__ void cp16(uint32_t dst, const void* src) {
    asm volatile("cp.async.cg.shared.global [%0], [%1], 16;"
                 :: "r"(dst), "l"(src) : "memory");
}
#define CP_COMMIT() asm volatile("cp.async.commit_group;" ::: "memory")
#define CP_WAIT0()  asm volatile("cp.async.wait_group 0;" ::: "memory")
#define CP_WAIT1()  asm volatile("cp.async.wait_group 1;" ::: "memory")

__device__ __forceinline__ void ldsm_x4_trans(uint32_t& d0, uint32_t& d1,
                                              uint32_t& d2, uint32_t& d3,
                                              uint32_t addr) {
    asm volatile(
        "ldmatrix.sync.aligned.m8n8.x4.trans.shared.b16 {%0,%1,%2,%3}, [%4];"
        : "=r"(d0), "=r"(d1), "=r"(d2), "=r"(d3) : "r"(addr));
}

// ---------------------------------------------------------------------------
// prep: x -> half; weights -> transposed half
// ---------------------------------------------------------------------------
__global__ void cvt_x(const float4* __restrict__ src, __half* __restrict__ dst,
                      int n4) {
    int i = blockIdx.x * 256 + threadIdx.x;
    if (i < n4) {
        float4 v = src[i];
        uint32_t* d = (uint32_t*)(dst + (size_t)i * 4);
        d[0] = packh2(v.x, v.y);
        d[1] = packh2(v.z, v.w);
    }
}

__global__ void prep_wqkvT(const float* __restrict__ W) {
    __shared__ float t[32][33];
    const int h = blockIdx.z;
    const int k0 = blockIdx.x << 5, n0 = blockIdx.y << 5;
    const int x = threadIdx.x, y0 = threadIdx.y;
#pragma unroll
    for (int yy = 0; yy < 32; yy += 8)
        t[y0 + yy][x] = W[(size_t)h * E_ * 192 + (size_t)(k0 + y0 + yy) * 192 +
                          n0 + x];
    __syncthreads();
#pragma unroll
    for (int yy = 0; yy < 32; yy += 8)
        g_wqkvT[(size_t)h * 192 * E_ + (size_t)(n0 + y0 + yy) * E_ + k0 + x] =
            __float2half_rn(t[x][y0 + yy]);
}

__global__ void prep_woutT(const float* __restrict__ W) {
    __shared__ float t[32][33];
    const int k0 = blockIdx.x << 5, n0 = blockIdx.y << 5;
    const int x = threadIdx.x, y0 = threadIdx.y;
#pragma unroll
    for (int yy = 0; yy < 32; yy += 8)
        t[y0 + yy][x] = W[(size_t)(k0 + y0 + yy) * E_ + n0 + x];
    __syncthreads();
#pragma unroll
    for (int yy = 0; yy < 32; yy += 8)
        g_woutT[(size_t)(n0 + y0 + yy) * E_ + k0 + x] =
            __float2half_rn(t[x][y0 + yy]);
}

// ---------------------------------------------------------------------------
// QKV: block 128 tokens x 192 cols, 16 warps 4m x 4n, warp 32x48, fp16 mma.
// K-chunk 64, 3-stage cp.async ring, ONE barrier per chunk.
// A smem [128][72]h, B smem [192][72]h per stage.
// ---------------------------------------------------------------------------
#define QKV_STAGE_H (128 * 72 + 192 * 72)   // 23040 halves
#define QKV_SMEM    (3 * QKV_STAGE_H * 2)   // 138240 bytes
__global__ __launch_bounds__(512) void qkv_kernel(const float* __restrict__ bqkv)
{
    extern __shared__ __half smh[];
    const uint32_t sbase = smem_u32(smh);
    const int tid = threadIdx.x;
    const int lane = tid & 31, wid = tid >> 5;
    const int gid = lane >> 2, tig = lane & 3;
    const int wm = wid >> 2, wn = wid & 3;

    const int n0 = blockIdx.x << 7;
    const int bh = blockIdx.y;
    const int h = bh & 15, b = bh >> 4;

    const __half* Asrc = g_xh + ((size_t)b * N_ + n0) * E_;
    const __half* Bsrc = g_wqkvT + (size_t)h * 192 * E_;

    auto stage = [&](int ch) {
        const int s = ch % 3;
        const uint32_t sa = sbase + (uint32_t)(s * QKV_STAGE_H * 2);
        const uint32_t sb = sa + 9216u * 2u;
        const int kc = ch * 64;
#pragma unroll
        for (int j = 0; j < 2; j++) {       // A: 128x8 = 1024 ops
            const int i = tid + j * 512;
            const int row = i >> 3, g8 = (i & 7) << 3;
            cp16(sa + (uint32_t)(row * 72 + g8) * 2,
                 Asrc + (size_t)row * E_ + kc + g8);
        }
#pragma unroll
        for (int j = 0; j < 3; j++) {       // B: 192x8 = 1536 ops
            const int i = tid + j * 512;
            const int row = i >> 3, g8 = (i & 7) << 3;
            cp16(sb + (uint32_t)(row * 72 + g8) * 2,
                 Bsrc + (size_t)row * E_ + kc + g8);
        }
    };

    float acc[2][6][4];
#pragma unroll
    for (int mt = 0; mt < 2; mt++)
#pragma unroll
        for (int nt = 0; nt < 6; nt++)
#pragma unroll
            for (int j = 0; j < 4; j++) acc[mt][nt][j] = 0.f;

    stage(0); CP_COMMIT();
    stage(1); CP_COMMIT();

    for (int ch = 0; ch < 16; ch++) {
        CP_WAIT1();                 // stage ch complete (<=1 group pending)
        __syncthreads();
        if (ch + 2 < 16) stage(ch + 2);
        CP_COMMIT();                // always commit (keeps wait arithmetic)
        const __half* sa = smh + (ch % 3) * QKV_STAGE_H;
        const __half* sb = sa + 9216;
#pragma unroll
        for (int ks = 0; ks < 4; ks++) {
            uint32_t a[2][4], bf[6][2];
#pragma unroll
            for (int mt = 0; mt < 2; mt++) {
                const __half* ap =
                    sa + (wm * 32 + mt * 16 + gid) * 72 + ks * 16 + 2 * tig;
                a[mt][0] = *(const uint32_t*)ap;
                a[mt][1] = *(const uint32_t*)(ap + 8 * 72);
                a[mt][2] = *(const uint32_t*)(ap + 8);
                a[mt][3] = *(const uint32_t*)(ap + 8 * 72 + 8);
            }
#pragma unroll
            for (int nt = 0; nt < 6; nt++) {
                const __half* bp =
                    sb + (wn * 48 + nt * 8 + gid) * 72 + ks * 16 + 2 * tig;
                bf[nt][0] = *(const uint32_t*)bp;
                bf[nt][1] = *(const uint32_t*)(bp + 8);
            }
#pragma unroll
            for (int mt = 0; mt < 2; mt++)
#pragma unroll
                for (int nt = 0; nt < 6; nt++)
                    mma_f16(acc[mt][nt], a[mt], bf[nt][0], bf[nt][1]);
        }
    }

    // epilogue: route to K/Q/V, bias, pre-scale Q, store half2
#pragma unroll
    for (int mt = 0; mt < 2; mt++) {
        const int row = wm * 32 + mt * 16 + gid;
#pragma unroll
        for (int nt = 0; nt < 6; nt++) {
            const int c = wn * 48 + nt * 8 + 2 * tig;
            const int part = c >> 6, cc = c & 63;
            __half* base = (part == 0) ? g_kh : (part == 1) ? g_qh : g_vh;
            const float sc = (part == 1) ? 0.125f : 1.f;
            const float b0 = bqkv[h * 192 + c], b1 = bqkv[h * 192 + c + 1];
            __half* p = base + ((size_t)bh * N_ + n0 + row) * HD_ + cc;
            *(uint32_t*)p = packh2((acc[mt][nt][0] + b0) * sc,
                                   (acc[mt][nt][1] + b1) * sc);
            *(uint32_t*)(p + (size_t)8 * HD_) =
                packh2((acc[mt][nt][2] + b0) * sc, (acc[mt][nt][3] + b1) * sc);
        }
    }
}

// ---------------------------------------------------------------------------
// Output projection: block 128 x 256, 16 warps 4m x 4n, warp 32x64.
// K-chunk 64, 3-stage ring, one barrier per chunk.
// ---------------------------------------------------------------------------
#define OUT_STAGE_H (128 * 72 + 256 * 72)   // 27648 halves
#define OUT_SMEM    (3 * OUT_STAGE_H * 2)   // 165888 bytes
__global__ __launch_bounds__(512) void outproj_kernel(
    const float* __restrict__ bout, float* __restrict__ out)
{
    extern __shared__ __half smh[];
    const uint32_t sbase = smem_u32(smh);
    const int tid = threadIdx.x;
    const int lane = tid & 31, wid = tid >> 5;
    const int gid = lane >> 2, tig = lane & 3;
    const int wm = wid >> 2, wn = wid & 3;

    const int r0 = blockIdx.x << 7;
    const int c0 = blockIdx.y << 8;

    const __half* Asrc = g_sah + (size_t)r0 * E_;
    const __half* Bsrc = g_woutT + (size_t)c0 * E_;

    auto stage = [&](int ch) {
        const int s = ch % 3;
        const uint32_t sa = sbase + (uint32_t)(s * OUT_STAGE_H * 2);
        const uint32_t sb = sa + 9216u * 2u;
        const int kc = ch * 64;
#pragma unroll
        for (int j = 0; j < 2; j++) {       // A: 1024 ops
            const int i = tid + j * 512;
            const int row = i >> 3, g8 = (i & 7) << 3;
            cp16(sa + (uint32_t)(row * 72 + g8) * 2,
                 Asrc + (size_t)row * E_ + kc + g8);
        }
#pragma unroll
        for (int j = 0; j < 4; j++) {       // B: 256x8 = 2048 ops
            const int i = tid + j * 512;
            const int row = i >> 3, g8 = (i & 7) << 3;
            cp16(sb + (uint32_t)(row * 72 + g8) * 2,
                 Bsrc + (size_t)row * E_ + kc + g8);
        }
    };

    float acc[2][8][4];
#pragma unroll
    for (int mt = 0; mt < 2; mt++)
#pragma unroll
        for (int nt = 0; nt < 8; nt++)
#pragma unroll
            for (int j = 0; j < 4; j++) acc[mt][nt][j] = 0.f;

    stage(0); CP_COMMIT();
    stage(1); CP_COMMIT();

    for (int ch = 0; ch < 16; ch++) {
        CP_WAIT1();
        __syncthreads();
        if (ch + 2 < 16) stage(ch + 2);
        CP_COMMIT();
        const __half* sa = smh + (ch % 3) * OUT_STAGE_H;
        const __half* sb = sa + 9216;
#pragma unroll
        for (int ks = 0; ks < 4; ks++) {
            uint32_t a[2][4], bf[8][2];
#pragma unroll
            for (int mt = 0; mt < 2; mt++) {
                const __half* ap =
                    sa + (wm * 32 + mt * 16 + gid) * 72 + ks * 16 + 2 * tig;
                a[mt][0] = *(const uint32_t*)ap;
                a[mt][1] = *(const uint32_t*)(ap + 8 * 72);
                a[mt][2] = *(const uint32_t*)(ap + 8);
                a[mt][3] = *(const uint32_t*)(ap + 8 * 72 + 8);
            }
#pragma unroll
            for (int nt = 0; nt < 8; nt++) {
                const __half* bp =
                    sb + (wn * 64 + nt * 8 + gid) * 72 + ks * 16 + 2 * tig;
                bf[nt][0] = *(const uint32_t*)bp;
                bf[nt][1] = *(const uint32_t*)(bp + 8);
            }
#pragma unroll
            for (int mt = 0; mt < 2; mt++)
#pragma unroll
                for (int nt = 0; nt < 8; nt++)
                    mma_f16(acc[mt][nt], a[mt], bf[nt][0], bf[nt][1]);
        }
    }

#pragma unroll
    for (int mt = 0; mt < 2; mt++) {
        const int row = r0 + wm * 32 + mt * 16 + gid;
#pragma unroll
        for (int nt = 0; nt < 8; nt++) {
            const int col = c0 + wn * 64 + nt * 8 + 2 * tig;
            const float b0 = bout[col], b1 = bout[col + 1];
            *(float2*)&out[(size_t)row * E_ + col] =
                make_float2(acc[mt][nt][0] + b0, acc[mt][nt][1] + b1);
            *(float2*)&out[(size_t)(row + 8) * E_ + col] =
                make_float2(acc[mt][nt][2] + b0, acc[mt][nt][3] + b1);
        }
    }
}

// ---------------------------------------------------------------------------
// Flash attention, fp16 mma: 8 warps, q-tile 256 (32 rows/warp).
// 3-stage K/V ring, one barrier per key-tile. P packs to A-frags directly;
// V fragments via ldmatrix.x4.trans.
// ---------------------------------------------------------------------------
#define ATTN_STAGE_H (2 * 64 * 72)              // 9216 halves (K + V tile)
#define ATTN_SMEM    (3 * ATTN_STAGE_H * 2)     // 55296 bytes
__global__ __launch_bounds__(256) void attn_kernel()
{
    extern __shared__ __half smh[];
    const uint32_t sbase = smem_u32(smh);
    const int tid = threadIdx.x;
    const int lane = tid & 31, w = tid >> 5;
    const int gid = lane >> 2, tig = lane & 3;
    const int qt = (int)(gridDim.x - 1) - (int)blockIdx.x;   // heavy first
    const int bh = blockIdx.y;
    const int b = bh >> 4, h = bh & 15;
    const int q0 = qt << 8;

    const __half* Kg = g_kh + (size_t)bh * N_ * HD_;
    const __half* Vg = g_vh + (size_t)bh * N_ * HD_;

    // Q fragments from global (pre-scaled + half)
    uint32_t Qa[4][2][4];
    {
        const __half* Qw = g_qh + ((size_t)bh * N_ + q0 + w * 32) * HD_;
#pragma unroll
        for (int kk = 0; kk < 4; kk++)
#pragma unroll
            for (int mt = 0; mt < 2; mt++) {
                const __half* p =
                    Qw + (size_t)(mt * 16 + gid) * HD_ + kk * 16 + 2 * tig;
                Qa[kk][mt][0] = *(const uint32_t*)p;
                Qa[kk][mt][1] = *(const uint32_t*)(p + 8 * HD_);
                Qa[kk][mt][2] = *(const uint32_t*)(p + 8);
                Qa[kk][mt][3] = *(const uint32_t*)(p + 8 * HD_ + 8);
            }
    }

    float m_[2][2] = {{NEG_INF, NEG_INF}, {NEG_INF, NEG_INF}};
    float l_[2][2] = {{0.f, 0.f}, {0.f, 0.f}};
    float Of[2][8][4];
#pragma unroll
    for (int mt = 0; mt < 2; mt++)
#pragma unroll
        for (int nt = 0; nt < 8; nt++)
#pragma unroll
            for (int j = 0; j < 4; j++) Of[mt][nt][j] = 0.f;

    const int wrow_max = q0 + w * 32 + 31;
    const int nkt = 4 * qt + 4;

    auto stage = [&](int kt) {
        const int s = kt % 3;
        const uint32_t ks = sbase + (uint32_t)(s * ATTN_STAGE_H * 2);
        const uint32_t vs = ks + (uint32_t)(64 * 72 * 2);
        const int k0 = kt << 6;
#pragma unroll
        for (int j = 0; j < 2; j++) {   // 512 ops each for K and V
            const int i = tid + j * 256;
            const int row = i >> 3, g8 = (i & 7) << 3;
            cp16(ks + (uint32_t)(row * 72 + g8) * 2,
                 Kg + (size_t)(k0 + row) * HD_ + g8);
            cp16(vs + (uint32_t)(row * 72 + g8) * 2,
                 Vg + (size_t)(k0 + row) * HD_ + g8);
        }
    };

    stage(0); CP_COMMIT();
    stage(1); CP_COMMIT();

    for (int kt = 0; kt < nkt; kt++) {
        CP_WAIT1();
        __syncthreads();
        if (kt + 2 < nkt) stage(kt + 2);
        CP_COMMIT();
        const __half* Ks = smh + (kt % 3) * ATTN_STAGE_H;
        const uint32_t vs_u32 =
            sbase + (uint32_t)((kt % 3) * ATTN_STAGE_H + 64 * 72) * 2;
        const int k0 = kt << 6;

        if (k0 <= wrow_max) {
            // ---- S = Q @ K^T ----
            float Sf[2][8][4];
#pragma unroll
            for (int mt = 0; mt < 2; mt++)
#pragma unroll
                for (int nt = 0; nt < 8; nt++)
#pragma unroll
                    for (int j = 0; j < 4; j++) Sf[mt][nt][j] = 0.f;

#pragma unroll
            for (int kk = 0; kk < 4; kk++)
#pragma unroll
                for (int nt = 0; nt < 8; nt++) {
                    const __half* bp =
                        Ks + (nt * 8 + gid) * 72 + kk * 16 + 2 * tig;
                    const uint32_t b0 = *(const uint32_t*)bp;
                    const uint32_t b1 = *(const uint32_t*)(bp + 8);
                    mma_f16(Sf[0][nt], Qa[kk][0], b0, b1);
                    mma_f16(Sf[1][nt], Qa[kk][1], b0, b1);
                }

            // ---- online softmax ----
#pragma unroll
            for (int mt = 0; mt < 2; mt++)
#pragma unroll
                for (int u = 0; u < 2; u++) {
                    const int row = q0 + w * 32 + mt * 16 + u * 8 + gid;
                    float tmax = NEG_INF;
#pragma unroll
                    for (int nt = 0; nt < 8; nt++)
#pragma unroll
                        for (int j = 0; j < 2; j++) {
                            const int col = k0 + nt * 8 + 2 * tig + j;
                            float s = Sf[mt][nt][u * 2 + j];
                            if (col > row) s = NEG_INF;
                            Sf[mt][nt][u * 2 + j] = s;
                            tmax = fmaxf(tmax, s);
                        }
                    tmax = fmaxf(tmax, __shfl_xor_sync(0xffffffffu, tmax, 1));
                    tmax = fmaxf(tmax, __shfl_xor_sync(0xffffffffu, tmax, 2));
                    const float mn = fmaxf(m_[mt][u], tmax);
                    const float alpha = __expf(m_[mt][u] - mn);
                    float rsum = 0.f;
#pragma unroll
                    for (int nt = 0; nt < 8; nt++)
#pragma unroll
                        for (int j = 0; j < 2; j++) {
                            const float p = __expf(Sf[mt][nt][u * 2 + j] - mn);
                            Sf[mt][nt][u * 2 + j] = p;
                            rsum += p;
                        }
                    rsum += __shfl_xor_sync(0xffffffffu, rsum, 1);
                    rsum += __shfl_xor_sync(0xffffffffu, rsum, 2);
                    l_[mt][u] = l_[mt][u] * alpha + rsum;
                    m_[mt][u] = mn;
#pragma unroll
                    for (int nt = 0; nt < 8; nt++)
#pragma unroll
                        for (int j = 0; j < 2; j++)
                            Of[mt][nt][u * 2 + j] *= alpha;
                }

            // ---- O += P @ V ----
#pragma unroll
            for (int kk = 0; kk < 4; kk++) {
                uint32_t Pa[2][4];
#pragma unroll
                for (int mt = 0; mt < 2; mt++) {
                    Pa[mt][0] = packh2(Sf[mt][2 * kk][0], Sf[mt][2 * kk][1]);
                    Pa[mt][1] = packh2(Sf[mt][2 * kk][2], Sf[mt][2 * kk][3]);
                    Pa[mt][2] = packh2(Sf[mt][2 * kk + 1][0], Sf[mt][2 * kk + 1][1]);
                    Pa[mt][3] = packh2(Sf[mt][2 * kk + 1][2], Sf[mt][2 * kk + 1][3]);
                }
#pragma unroll
                for (int j = 0; j < 4; j++) {
                    const int vrow = kk * 16 + (lane & 15);
                    const int vcol = j * 16 + ((lane >> 4) << 3);
                    uint32_t d0, d1, d2, d3;
                    ldsm_x4_trans(d0, d1, d2, d3,
                                  vs_u32 + (uint32_t)(vrow * 72 + vcol) * 2);
                    mma_f16(Of[0][2 * j], Pa[0], d0, d1);
                    mma_f16(Of[1][2 * j], Pa[1], d0, d1);
                    mma_f16(Of[0][2 * j + 1], Pa[0], d2, d3);
                    mma_f16(Of[1][2 * j + 1], Pa[1], d2, d3);
                }
            }
        }
    }

    // ---- normalize + write heads-concatenated sa[b, n, h*64+d] (half) ----
#pragma unroll
    for (int mt = 0; mt < 2; mt++)
#pragma unroll
        for (int u = 0; u < 2; u++) {
            const float inv = 1.f / l_[mt][u];
            __half* dst = g_sah +
                ((size_t)(b * N_ + q0 + w * 32 + mt * 16 + u * 8 + gid)) * E_ +
                h * HD_;
#pragma unroll
            for (int nt = 0; nt < 8; nt++) {
                const int col = nt * 8 + 2 * tig;
                *(uint32_t*)&dst[col] = packh2(Of[mt][nt][u * 2] * inv,
                                               Of[mt][nt][u * 2 + 1] * inv);
            }
        }
}

// ---------------------------------------------------------------------------
extern "C" void kernel_launch(void* const* d_in, const int* in_sizes, int n_in,
                              void* d_out, int out_size)
{
    const float* x = nullptr;
    const float* Wqkv = nullptr;
    const float* bqkv = nullptr;
    const float* Wout = nullptr;
    const float* bout = nullptr;
    for (int i = 0; i < n_in; i++) {
        switch (in_sizes[i]) {
            case B_ * N_ * E_:        x    = (const float*)d_in[i]; break; // 4194304
            case H_ * E_ * 3 * HD_:   Wqkv = (const float*)d_in[i]; break; // 3145728
            case H_ * 3 * HD_:        bqkv = (const float*)d_in[i]; break; // 3072
            case E_ * E_:             Wout = (const float*)d_in[i]; break; // 1048576
            case E_:                  bout = (const float*)d_in[i]; break; // 1024
            default: break;
        }
    }
    float* out = (float*)d_out;

    cudaFuncSetAttribute(qkv_kernel, cudaFuncAttributeMaxDynamicSharedMemorySize,
                         QKV_SMEM);
    cudaFuncSetAttribute(outproj_kernel,
                         cudaFuncAttributeMaxDynamicSharedMemorySize, OUT_SMEM);
    cudaFuncSetAttribute(attn_kernel, cudaFuncAttributeMaxDynamicSharedMemorySize,
                         ATTN_SMEM);

    __half* d_xh;
    cudaGetSymbolAddress((void**)&d_xh, g_xh);

    cvt_x<<<4096, 256>>>((const float4*)x, d_xh, 1048576);
    prep_wqkvT<<<dim3(32, 6, 16), dim3(32, 8)>>>(Wqkv);
    prep_woutT<<<dim3(32, 32), dim3(32, 8)>>>(Wout);

    qkv_kernel<<<dim3(N_ / 128, B_ * H_), 512, QKV_SMEM>>>(bqkv);
    attn_kernel<<<dim3(N_ / 256, B_ * H_), 256, ATTN_SMEM>>>();
    outproj_kernel<<<dim3((B_ * N_) / 128, E_ / 256), 512, OUT_SMEM>>>(bout, out);
}

// round 16
// speedup vs baseline: 11.2084x; 1.0989x over previous
#include <cuda_runtime.h>
#include <cuda_fp16.h>
#include <math.h>
#include <stdint.h>

#define B_  2
#define N_  2048
#define E_  1024
#define H_  16
#define HD_ 64

#define NEG_INF __int_as_float(0xff800000)

// Scratch (device globals — no runtime allocation allowed)
__device__ __half g_qh[(size_t)B_ * H_ * N_ * HD_];   // pre-scaled by 0.125
__device__ __half g_kh[(size_t)B_ * H_ * N_ * HD_];
__device__ __half g_vh[(size_t)B_ * H_ * N_ * HD_];
__device__ __half g_sah[(size_t)B_ * N_ * E_];
__device__ __half g_xh[(size_t)B_ * N_ * E_];
__device__ __half g_wqkvT[(size_t)H_ * 192 * E_];     // [h][n=192][k=1024]
__device__ __half g_woutT[(size_t)E_ * E_];           // [n][k]

// ---------------------------------------------------------------------------
// helpers
// ---------------------------------------------------------------------------
__device__ __forceinline__ uint32_t packh2(float a, float b) {
    __half2 h = __floats2half2_rn(a, b);
    return *(uint32_t*)&h;
}

__device__ __forceinline__ void mma_f16(float (&d)[4], const uint32_t (&a)[4],
                                        uint32_t b0, uint32_t b1) {
    asm volatile(
        "mma.sync.aligned.m16n8k16.row.col.f32.f16.f16.f32 "
        "{%0,%1,%2,%3},{%4,%5,%6,%7},{%8,%9},{%0,%1,%2,%3};"
        : "+f"(d[0]), "+f"(d[1]), "+f"(d[2]), "+f"(d[3])
        : "r"(a[0]), "r"(a[1]), "r"(a[2]), "r"(a[3]), "r"(b0), "r"(b1));
}

__device__ __forceinline__ uint32_t smem_u32(const void* p) {
    uint32_t a;
    asm("{ .reg .u64 t; cvta.to.shared.u64 t, %1; cvt.u32.u64 %0, t; }"
        : "=r"(a) : "l"(p));
    return a;
}

__device__ __forceinline__ void cp16(uint32_t dst, const void* src) {
    asm volatile("cp.async.cg.shared.global [%0], [%1], 16;"
                 :: "r"(dst), "l"(src) : "memory");
}
#define CP_COMMIT() asm volatile("cp.async.commit_group;" ::: "memory")
#define CP_WAIT0()  asm volatile("cp.async.wait_group 0;" ::: "memory")
#define CP_WAIT1()  asm volatile("cp.async.wait_group 1;" ::: "memory")

__device__ __forceinline__ void ldsm_x4_trans(uint32_t& d0, uint32_t& d1,
                                              uint32_t& d2, uint32_t& d3,
                                              uint32_t addr) {
    asm volatile(
        "ldmatrix.sync.aligned.m8n8.x4.trans.shared.b16 {%0,%1,%2,%3}, [%4];"
        : "=r"(d0), "=r"(d1), "=r"(d2), "=r"(d3) : "r"(addr));
}

// ---------------------------------------------------------------------------
// prep: x -> half; weights -> transposed half
// ---------------------------------------------------------------------------
__global__ void cvt_x(const float4* __restrict__ src, __half* __restrict__ dst,
                      int n4) {
    int i = blockIdx.x * 256 + threadIdx.x;
    if (i < n4) {
        float4 v = src[i];
        uint32_t* d = (uint32_t*)(dst + (size_t)i * 4);
        d[0] = packh2(v.x, v.y);
        d[1] = packh2(v.z, v.w);
    }
}

__global__ void prep_wqkvT(const float* __restrict__ W) {
    __shared__ float t[32][33];
    const int h = blockIdx.z;
    const int k0 = blockIdx.x << 5, n0 = blockIdx.y << 5;
    const int x = threadIdx.x, y0 = threadIdx.y;
#pragma unroll
    for (int yy = 0; yy < 32; yy += 8)
        t[y0 + yy][x] = W[(size_t)h * E_ * 192 + (size_t)(k0 + y0 + yy) * 192 +
                          n0 + x];
    __syncthreads();
#pragma unroll
    for (int yy = 0; yy < 32; yy += 8)
        g_wqkvT[(size_t)h * 192 * E_ + (size_t)(n0 + y0 + yy) * E_ + k0 + x] =
            __float2half_rn(t[x][y0 + yy]);
}

__global__ void prep_woutT(const float* __restrict__ W) {
    __shared__ float t[32][33];
    const int k0 = blockIdx.x << 5, n0 = blockIdx.y << 5;
    const int x = threadIdx.x, y0 = threadIdx.y;
#pragma unroll
    for (int yy = 0; yy < 32; yy += 8)
        t[y0 + yy][x] = W[(size_t)(k0 + y0 + yy) * E_ + n0 + x];
    __syncthreads();
#pragma unroll
    for (int yy = 0; yy < 32; yy += 8)
        g_woutT[(size_t)(n0 + y0 + yy) * E_ + k0 + x] =
            __float2half_rn(t[x][y0 + yy]);
}

// ---------------------------------------------------------------------------
// QKV: block 128 tokens x 96 cols, 8 warps 4m x 2n, warp 32x48, fp16 mma.
// K-chunk 64, 2-stage cp.async ring, ONE barrier per chunk, 3 CTAs/SM.
// ---------------------------------------------------------------------------
#define QKV_STAGE_H ((128 + 96) * 72)       // 16128 halves
#define QKV_SMEM    (2 * QKV_STAGE_H * 2)   // 64512 bytes
__global__ __launch_bounds__(256, 3) void qkv_kernel(const float* __restrict__ bqkv)
{
    extern __shared__ __half smh[];
    const uint32_t sbase = smem_u32(smh);
    const int tid = threadIdx.x;
    const int lane = tid & 31, wid = tid >> 5;
    const int gid = lane >> 2, tig = lane & 3;
    const int wm = wid & 3, wn = wid >> 2;

    const int n0 = blockIdx.x << 7;
    const int y  = blockIdx.y;              // 96-col half
    const int bh = blockIdx.z;
    const int h = bh & 15, b = bh >> 4;

    const __half* Asrc = g_xh + ((size_t)b * N_ + n0) * E_;
    const __half* Bsrc = g_wqkvT + (size_t)h * 192 * E_ + (size_t)(y * 96) * E_;

    auto stage = [&](int ch) {
        const int s = ch & 1;
        const uint32_t sa = sbase + (uint32_t)(s * QKV_STAGE_H * 2);
        const uint32_t sb = sa + (uint32_t)(128 * 72 * 2);
        const int kc = ch * 64;
#pragma unroll
        for (int j = 0; j < 4; j++) {       // A: 128x8 = 1024 ops
            const int i = tid + j * 256;
            const int row = i >> 3, g8 = (i & 7) << 3;
            cp16(sa + (uint32_t)(row * 72 + g8) * 2,
                 Asrc + (size_t)row * E_ + kc + g8);
        }
#pragma unroll
        for (int j = 0; j < 3; j++) {       // B: 96x8 = 768 ops
            const int i = tid + j * 256;
            const int row = i >> 3, g8 = (i & 7) << 3;
            cp16(sb + (uint32_t)(row * 72 + g8) * 2,
                 Bsrc + (size_t)row * E_ + kc + g8);
        }
    };

    float acc[2][6][4];
#pragma unroll
    for (int mt = 0; mt < 2; mt++)
#pragma unroll
        for (int nt = 0; nt < 6; nt++)
#pragma unroll
            for (int j = 0; j < 4; j++) acc[mt][nt][j] = 0.f;

    stage(0); CP_COMMIT();

    for (int ch = 0; ch < 16; ch++) {
        CP_WAIT0();                 // stage ch arrived
        __syncthreads();            // + everyone done consuming ch-1
        if (ch + 1 < 16) { stage(ch + 1); CP_COMMIT(); }
        const __half* sa = smh + (ch & 1) * QKV_STAGE_H;
        const __half* sb = sa + 128 * 72;
#pragma unroll
        for (int ks = 0; ks < 4; ks++) {
            uint32_t a[2][4], bf[6][2];
#pragma unroll
            for (int mt = 0; mt < 2; mt++) {
                const __half* ap =
                    sa + (wm * 32 + mt * 16 + gid) * 72 + ks * 16 + 2 * tig;
                a[mt][0] = *(const uint32_t*)ap;
                a[mt][1] = *(const uint32_t*)(ap + 8 * 72);
                a[mt][2] = *(const uint32_t*)(ap + 8);
                a[mt][3] = *(const uint32_t*)(ap + 8 * 72 + 8);
            }
#pragma unroll
            for (int nt = 0; nt < 6; nt++) {
                const __half* bp =
                    sb + (wn * 48 + nt * 8 + gid) * 72 + ks * 16 + 2 * tig;
                bf[nt][0] = *(const uint32_t*)bp;
                bf[nt][1] = *(const uint32_t*)(bp + 8);
            }
#pragma unroll
            for (int mt = 0; mt < 2; mt++)
#pragma unroll
                for (int nt = 0; nt < 6; nt++)
                    mma_f16(acc[mt][nt], a[mt], bf[nt][0], bf[nt][1]);
        }
    }

    // epilogue: route to K/Q/V, bias, pre-scale Q, store half2
#pragma unroll
    for (int mt = 0; mt < 2; mt++) {
        const int row = wm * 32 + mt * 16 + gid;
#pragma unroll
        for (int nt = 0; nt < 6; nt++) {
            const int c = y * 96 + wn * 48 + nt * 8 + 2 * tig;
            const int part = c >> 6, cc = c & 63;
            __half* base = (part == 0) ? g_kh : (part == 1) ? g_qh : g_vh;
            const float sc = (part == 1) ? 0.125f : 1.f;
            const float b0 = bqkv[h * 192 + c], b1 = bqkv[h * 192 + c + 1];
            __half* p = base + ((size_t)bh * N_ + n0 + row) * HD_ + cc;
            *(uint32_t*)p = packh2((acc[mt][nt][0] + b0) * sc,
                                   (acc[mt][nt][1] + b1) * sc);
            *(uint32_t*)(p + (size_t)8 * HD_) =
                packh2((acc[mt][nt][2] + b0) * sc, (acc[mt][nt][3] + b1) * sc);
        }
    }
}

// ---------------------------------------------------------------------------
// Output projection: block 128 x 128, 8 warps 4m x 2n, warp 32x64.
// K-chunk 64, 2-stage ring, one barrier per chunk, 2 CTAs/SM.
// ---------------------------------------------------------------------------
#define OUT_STAGE_H ((128 + 128) * 72)      // 18432 halves
#define OUT_SMEM    (2 * OUT_STAGE_H * 2)   // 73728 bytes
__global__ __launch_bounds__(256, 2) void outproj_kernel(
    const float* __restrict__ bout, float* __restrict__ out)
{
    extern __shared__ __half smh[];
    const uint32_t sbase = smem_u32(smh);
    const int tid = threadIdx.x;
    const int lane = tid & 31, wid = tid >> 5;
    const int gid = lane >> 2, tig = lane & 3;
    const int wm = wid & 3, wn = wid >> 2;

    const int r0 = blockIdx.x << 7;
    const int c0 = blockIdx.y << 7;

    const __half* Asrc = g_sah + (size_t)r0 * E_;
    const __half* Bsrc = g_woutT + (size_t)c0 * E_;

    auto stage = [&](int ch) {
        const int s = ch & 1;
        const uint32_t sa = sbase + (uint32_t)(s * OUT_STAGE_H * 2);
        const uint32_t sb = sa + (uint32_t)(128 * 72 * 2);
        const int kc = ch * 64;
#pragma unroll
        for (int j = 0; j < 4; j++) {       // A: 1024 ops
            const int i = tid + j * 256;
            const int row = i >> 3, g8 = (i & 7) << 3;
            cp16(sa + (uint32_t)(row * 72 + g8) * 2,
                 Asrc + (size_t)row * E_ + kc + g8);
        }
#pragma unroll
        for (int j = 0; j < 4; j++) {       // B: 128x8 = 1024 ops
            const int i = tid + j * 256;
            const int row = i >> 3, g8 = (i & 7) << 3;
            cp16(sb + (uint32_t)(row * 72 + g8) * 2,
                 Bsrc + (size_t)row * E_ + kc + g8);
        }
    };

    float acc[2][8][4];
#pragma unroll
    for (int mt = 0; mt < 2; mt++)
#pragma unroll
        for (int nt = 0; nt < 8; nt++)
#pragma unroll
            for (int j = 0; j < 4; j++) acc[mt][nt][j] = 0.f;

    stage(0); CP_COMMIT();

    for (int ch = 0; ch < 16; ch++) {
        CP_WAIT0();
        __syncthreads();
        if (ch + 1 < 16) { stage(ch + 1); CP_COMMIT(); }
        const __half* sa = smh + (ch & 1) * OUT_STAGE_H;
        const __half* sb = sa + 128 * 72;
#pragma unroll
        for (int ks = 0; ks < 4; ks++) {
            uint32_t a[2][4], bf[8][2];
#pragma unroll
            for (int mt = 0; mt < 2; mt++) {
                const __half* ap =
                    sa + (wm * 32 + mt * 16 + gid) * 72 + ks * 16 + 2 * tig;
                a[mt][0] = *(const uint32_t*)ap;
                a[mt][1] = *(const uint32_t*)(ap + 8 * 72);
                a[mt][2] = *(const uint32_t*)(ap + 8);
                a[mt][3] = *(const uint32_t*)(ap + 8 * 72 + 8);
            }
#pragma unroll
            for (int nt = 0; nt < 8; nt++) {
                const __half* bp =
                    sb + (wn * 64 + nt * 8 + gid) * 72 + ks * 16 + 2 * tig;
                bf[nt][0] = *(const uint32_t*)bp;
                bf[nt][1] = *(const uint32_t*)(bp + 8);
            }
#pragma unroll
            for (int mt = 0; mt < 2; mt++)
#pragma unroll
                for (int nt = 0; nt < 8; nt++)
                    mma_f16(acc[mt][nt], a[mt], bf[nt][0], bf[nt][1]);
        }
    }

#pragma unroll
    for (int mt = 0; mt < 2; mt++) {
        const int row = r0 + wm * 32 + mt * 16 + gid;
#pragma unroll
        for (int nt = 0; nt < 8; nt++) {
            const int col = c0 + wn * 64 + nt * 8 + 2 * tig;
            const float b0 = bout[col], b1 = bout[col + 1];
            *(float2*)&out[(size_t)row * E_ + col] =
                make_float2(acc[mt][nt][0] + b0, acc[mt][nt][1] + b1);
            *(float2*)&out[(size_t)(row + 8) * E_ + col] =
                make_float2(acc[mt][nt][2] + b0, acc[mt][nt][3] + b1);
        }
    }
}

// ---------------------------------------------------------------------------
// Flash attention, fp16 mma (UNCHANGED from round-14 winner): 8 warps,
// q-tile 256 (32 rows/warp), 3-stage K/V ring, one barrier per key-tile.
// ---------------------------------------------------------------------------
#define ATTN_STAGE_H (2 * 64 * 72)              // 9216 halves (K + V tile)
#define ATTN_SMEM    (3 * ATTN_STAGE_H * 2)     // 55296 bytes
__global__ __launch_bounds__(256) void attn_kernel()
{
    extern __shared__ __half smh[];
    const uint32_t sbase = smem_u32(smh);
    const int tid = threadIdx.x;
    const int lane = tid & 31, w = tid >> 5;
    const int gid = lane >> 2, tig = lane & 3;
    const int qt = (int)(gridDim.x - 1) - (int)blockIdx.x;   // heavy first
    const int bh = blockIdx.y;
    const int b = bh >> 4, h = bh & 15;
    const int q0 = qt << 8;

    const __half* Kg = g_kh + (size_t)bh * N_ * HD_;
    const __half* Vg = g_vh + (size_t)bh * N_ * HD_;

    // Q fragments from global (pre-scaled + half)
    uint32_t Qa[4][2][4];
    {
        const __half* Qw = g_qh + ((size_t)bh * N_ + q0 + w * 32) * HD_;
#pragma unroll
        for (int kk = 0; kk < 4; kk++)
#pragma unroll
            for (int mt = 0; mt < 2; mt++) {
                const __half* p =
                    Qw + (size_t)(mt * 16 + gid) * HD_ + kk * 16 + 2 * tig;
                Qa[kk][mt][0] = *(const uint32_t*)p;
                Qa[kk][mt][1] = *(const uint32_t*)(p + 8 * HD_);
                Qa[kk][mt][2] = *(const uint32_t*)(p + 8);
                Qa[kk][mt][3] = *(const uint32_t*)(p + 8 * HD_ + 8);
            }
    }

    float m_[2][2] = {{NEG_INF, NEG_INF}, {NEG_INF, NEG_INF}};
    float l_[2][2] = {{0.f, 0.f}, {0.f, 0.f}};
    float Of[2][8][4];
#pragma unroll
    for (int mt = 0; mt < 2; mt++)
#pragma unroll
        for (int nt = 0; nt < 8; nt++)
#pragma unroll
            for (int j = 0; j < 4; j++) Of[mt][nt][j] = 0.f;

    const int wrow_max = q0 + w * 32 + 31;
    const int nkt = 4 * qt + 4;

    auto stage = [&](int kt) {
        const int s = kt % 3;
        const uint32_t ks = sbase + (uint32_t)(s * ATTN_STAGE_H * 2);
        const uint32_t vs = ks + (uint32_t)(64 * 72 * 2);
        const int k0 = kt << 6;
#pragma unroll
        for (int j = 0; j < 2; j++) {   // 512 ops each for K and V
            const int i = tid + j * 256;
            const int row = i >> 3, g8 = (i & 7) << 3;
            cp16(ks + (uint32_t)(row * 72 + g8) * 2,
                 Kg + (size_t)(k0 + row) * HD_ + g8);
            cp16(vs + (uint32_t)(row * 72 + g8) * 2,
                 Vg + (size_t)(k0 + row) * HD_ + g8);
        }
    };

    stage(0); CP_COMMIT();
    stage(1); CP_COMMIT();

    for (int kt = 0; kt < nkt; kt++) {
        CP_WAIT1();
        __syncthreads();
        if (kt + 2 < nkt) stage(kt + 2);
        CP_COMMIT();
        const __half* Ks = smh + (kt % 3) * ATTN_STAGE_H;
        const uint32_t vs_u32 =
            sbase + (uint32_t)((kt % 3) * ATTN_STAGE_H + 64 * 72) * 2;
        const int k0 = kt << 6;

        if (k0 <= wrow_max) {
            // ---- S = Q @ K^T ----
            float Sf[2][8][4];
#pragma unroll
            for (int mt = 0; mt < 2; mt++)
#pragma unroll
                for (int nt = 0; nt < 8; nt++)
#pragma unroll
                    for (int j = 0; j < 4; j++) Sf[mt][nt][j] = 0.f;

#pragma unroll
            for (int kk = 0; kk < 4; kk++)
#pragma unroll
                for (int nt = 0; nt < 8; nt++) {
                    const __half* bp =
                        Ks + (nt * 8 + gid) * 72 + kk * 16 + 2 * tig;
                    const uint32_t b0 = *(const uint32_t*)bp;
                    const uint32_t b1 = *(const uint32_t*)(bp + 8);
                    mma_f16(Sf[0][nt], Qa[kk][0], b0, b1);
                    mma_f16(Sf[1][nt], Qa[kk][1], b0, b1);
                }

            // ---- online softmax ----
#pragma unroll
            for (int mt = 0; mt < 2; mt++)
#pragma unroll
                for (int u = 0; u < 2; u++) {
                    const int row = q0 + w * 32 + mt * 16 + u * 8 + gid;
                    float tmax = NEG_INF;
#pragma unroll
                    for (int nt = 0; nt < 8; nt++)
#pragma unroll
                        for (int j = 0; j < 2; j++) {
                            const int col = k0 + nt * 8 + 2 * tig + j;
                            float s = Sf[mt][nt][u * 2 + j];
                            if (col > row) s = NEG_INF;
                            Sf[mt][nt][u * 2 + j] = s;
                            tmax = fmaxf(tmax, s);
                        }
                    tmax = fmaxf(tmax, __shfl_xor_sync(0xffffffffu, tmax, 1));
                    tmax = fmaxf(tmax, __shfl_xor_sync(0xffffffffu, tmax, 2));
                    const float mn = fmaxf(m_[mt][u], tmax);
                    const float alpha = __expf(m_[mt][u] - mn);
                    float rsum = 0.f;
#pragma unroll
                    for (int nt = 0; nt < 8; nt++)
#pragma unroll
                        for (int j = 0; j < 2; j++) {
                            const float p = __expf(Sf[mt][nt][u * 2 + j] - mn);
                            Sf[mt][nt][u * 2 + j] = p;
                            rsum += p;
                        }
                    rsum += __shfl_xor_sync(0xffffffffu, rsum, 1);
                    rsum += __shfl_xor_sync(0xffffffffu, rsum, 2);
                    l_[mt][u] = l_[mt][u] * alpha + rsum;
                    m_[mt][u] = mn;
#pragma unroll
                    for (int nt = 0; nt < 8; nt++)
#pragma unroll
                        for (int j = 0; j < 2; j++)
                            Of[mt][nt][u * 2 + j] *= alpha;
                }

            // ---- O += P @ V ----
#pragma unroll
            for (int kk = 0; kk < 4; kk++) {
                uint32_t Pa[2][4];
#pragma unroll
                for (int mt = 0; mt < 2; mt++) {
                    Pa[mt][0] = packh2(Sf[mt][2 * kk][0], Sf[mt][2 * kk][1]);
                    Pa[mt][1] = packh2(Sf[mt][2 * kk][2], Sf[mt][2 * kk][3]);
                    Pa[mt][2] = packh2(Sf[mt][2 * kk + 1][0], Sf[mt][2 * kk + 1][1]);
                    Pa[mt][3] = packh2(Sf[mt][2 * kk + 1][2], Sf[mt][2 * kk + 1][3]);
                }
#pragma unroll
                for (int j = 0; j < 4; j++) {
                    const int vrow = kk * 16 + (lane & 15);
                    const int vcol = j * 16 + ((lane >> 4) << 3);
                    uint32_t d0, d1, d2, d3;
                    ldsm_x4_trans(d0, d1, d2, d3,
                                  vs_u32 + (uint32_t)(vrow * 72 + vcol) * 2);
                    mma_f16(Of[0][2 * j], Pa[0], d0, d1);
                    mma_f16(Of[1][2 * j], Pa[1], d0, d1);
                    mma_f16(Of[0][2 * j + 1], Pa[0], d2, d3);
                    mma_f16(Of[1][2 * j + 1], Pa[1], d2, d3);
                }
            }
        }
    }

    // ---- normalize + write heads-concatenated sa[b, n, h*64+d] (half) ----
#pragma unroll
    for (int mt = 0; mt < 2; mt++)
#pragma unroll
        for (int u = 0; u < 2; u++) {
            const float inv = 1.f / l_[mt][u];
            __half* dst = g_sah +
                ((size_t)(b * N_ + q0 + w * 32 + mt * 16 + u * 8 + gid)) * E_ +
                h * HD_;
#pragma unroll
            for (int nt = 0; nt < 8; nt++) {
                const int col = nt * 8 + 2 * tig;
                *(uint32_t*)&dst[col] = packh2(Of[mt][nt][u * 2] * inv,
                                               Of[mt][nt][u * 2 + 1] * inv);
            }
        }
}

// ---------------------------------------------------------------------------
extern "C" void kernel_launch(void* const* d_in, const int* in_sizes, int n_in,
                              void* d_out, int out_size)
{
    const float* x = nullptr;
    const float* Wqkv = nullptr;
    const float* bqkv = nullptr;
    const float* Wout = nullptr;
    const float* bout = nullptr;
    for (int i = 0; i < n_in; i++) {
        switch (in_sizes[i]) {
            case B_ * N_ * E_:        x    = (const float*)d_in[i]; break; // 4194304
            case H_ * E_ * 3 * HD_:   Wqkv = (const float*)d_in[i]; break; // 3145728
            case H_ * 3 * HD_:        bqkv = (const float*)d_in[i]; break; // 3072
            case E_ * E_:             Wout = (const float*)d_in[i]; break; // 1048576
            case E_:                  bout = (const float*)d_in[i]; break; // 1024
            default: break;
        }
    }
    float* out = (float*)d_out;

    cudaFuncSetAttribute(qkv_kernel, cudaFuncAttributeMaxDynamicSharedMemorySize,
                         QKV_SMEM);
    cudaFuncSetAttribute(outproj_kernel,
                         cudaFuncAttributeMaxDynamicSharedMemorySize, OUT_SMEM);
    cudaFuncSetAttribute(attn_kernel, cudaFuncAttributeMaxDynamicSharedMemorySize,
                         ATTN_SMEM);

    __half* d_xh;
    cudaGetSymbolAddress((void**)&d_xh, g_xh);

    cvt_x<<<4096, 256>>>((const float4*)x, d_xh, 1048576);
    prep_wqkvT<<<dim3(32, 6, 16), dim3(32, 8)>>>(Wqkv);
    prep_woutT<<<dim3(32, 32), dim3(32, 8)>>>(Wout);

    qkv_kernel<<<dim3(N_ / 128, 2, B_ * H_), 256, QKV_SMEM>>>(bqkv);
    attn_kernel<<<dim3(N_ / 256, B_ * H_), 256, ATTN_SMEM>>>();
    outproj_kernel<<<dim3((B_ * N_) / 128, E_ / 128), 256, OUT_SMEM>>>(bout, out);
}